// round 11
// baseline (speedup 1.0000x reference)
#include <cuda_runtime.h>
#include <cuda_bf16.h>
#include <math.h>
#include <stdint.h>

#define NN     30000
#define NN_PAD 30080
#define EE     480000
#define NFD    128
#define EFD    64
#define HID    256
#define LL     4
#define NH     8
#define DD     32
#define TILE   64

#define OFF_H 0
#define OFF_G (NN*HID)
#define OFF_C (NN*HID + HID)
#define OFF_S (NN*HID + HID + NN)

#define PLANE ((size_t)NN * HID)

#define STAGE_BYTES 30720
#define A_ROW_B 80

// ---------------- static device scratch ----------------
__device__ float d_h   [NN*HID];
__device__ float d_QKVS[(size_t)4*NN*HID];   // planes: Q | K | V | SK
__device__ __align__(16) unsigned short d_AbfH[(size_t)NN_PAD*HID];
__device__ __align__(16) unsigned short d_AbfL[(size_t)NN_PAD*HID];
__device__ __align__(16) unsigned short d_WtH[(size_t)LL*1024*HID];  // [l][n][k]
__device__ __align__(16) unsigned short d_WtL[(size_t)LL*1024*HID];
__device__ __align__(16) unsigned short d_Wt1H[128*HID];             // cp_W1^T
__device__ __align__(16) unsigned short d_Wt1L[128*HID];
__device__ float d_bpack[LL*1024];
__device__ float d_Wcomb [LL*EFD*HID];
__device__ float d_WcombT[LL*HID*EFD];
__device__ float d_bcomb[LL*HID];
__device__ float d_T1[NN*(HID/2)];
__device__ int   d_counts[NN];
__device__ int   d_cursor[NN];
__device__ int   d_rowptr[NN+1];
__device__ int   d_perm[EE];

// ---------------- small helpers ----------------
__device__ __forceinline__ float warp_sum(float v) {
    v += __shfl_xor_sync(0xffffffffu, v, 16);
    v += __shfl_xor_sync(0xffffffffu, v, 8);
    v += __shfl_xor_sync(0xffffffffu, v, 4);
    v += __shfl_xor_sync(0xffffffffu, v, 2);
    v += __shfl_xor_sync(0xffffffffu, v, 1);
    return v;
}
__device__ __forceinline__ unsigned short bf16_bits(float f) {
    __nv_bfloat16 b = __float2bfloat16(f);
    return *(unsigned short*)&b;
}
__device__ __forceinline__ float bf16_round(float f) {
    return __bfloat162float(__float2bfloat16(f));
}

// ---------------- PTX wrappers (plain sm_80+ features only) ----------------
__device__ __forceinline__ void cp_async16(uint32_t saddr, const void* gptr) {
    asm volatile("cp.async.cg.shared.global [%0], [%1], 16;" :: "r"(saddr), "l"(gptr));
}
__device__ __forceinline__ void cp_commit() {
    asm volatile("cp.async.commit_group;");
}
template <int N>
__device__ __forceinline__ void cp_wait() {
    asm volatile("cp.async.wait_group %0;" :: "n"(N));
}
__device__ __forceinline__ void ldsm4(uint32_t* r, uint32_t addr) {
    asm volatile("ldmatrix.sync.aligned.m8n8.x4.shared.b16 {%0,%1,%2,%3}, [%4];"
                 : "=r"(r[0]), "=r"(r[1]), "=r"(r[2]), "=r"(r[3]) : "r"(addr));
}
__device__ __forceinline__ void mma16816(float* c, const uint32_t* a, uint32_t b0, uint32_t b1) {
    asm volatile(
        "mma.sync.aligned.m16n8k16.row.col.f32.bf16.bf16.f32 "
        "{%0,%1,%2,%3}, {%4,%5,%6,%7}, {%8,%9}, {%0,%1,%2,%3};"
        : "+f"(c[0]), "+f"(c[1]), "+f"(c[2]), "+f"(c[3])
        : "r"(a[0]), "r"(a[1]), "r"(a[2]), "r"(a[3]), "r"(b0), "r"(b1));
}

// ---------------- tensor-core GEMM (bf16 hi/lo split, fp32 acc) ----------------
// mode 0: C = QKVS planes; logical [NN_PAD][1024] = A[.,256] @ Wt[1024][256]^T + bias
// mode 1: C = T1 [NN][128] = relu(A @ Wt1^T + bias)
__global__ __launch_bounds__(256) void hgemm_kernel(
    const unsigned short* __restrict__ AH, const unsigned short* __restrict__ AL,
    const unsigned short* __restrict__ BH, const unsigned short* __restrict__ BL,
    const float* __restrict__ bias, float* __restrict__ C, int mode)
{
    extern __shared__ unsigned char sm[];
    uint32_t sbase = (uint32_t)__cvta_generic_to_shared(sm);
    const int tid  = threadIdx.x;
    const int wid  = tid >> 5, lane = tid & 31;
    const int warpM = wid & 3, warpN = wid >> 2;
    const int rowBase = blockIdx.y * 128;
    const int colBase = blockIdx.x * 64;

    float acc[2][4][4];
#pragma unroll
    for (int mi = 0; mi < 2; mi++)
#pragma unroll
        for (int nf = 0; nf < 4; nf++)
#pragma unroll
            for (int k = 0; k < 4; k++) acc[mi][nf][k] = 0.f;

    const int ar  = tid >> 1;
    const int as0 = (tid & 1) * 2;
    const int br  = tid >> 2;
    const int bs  = tid & 3;

    auto issue = [&](int ch, int stage) {
        uint32_t s0 = sbase + stage * STAGE_BYTES;
        const unsigned short* gAH = AH + (size_t)(rowBase + ar) * HID + ch * 32;
        const unsigned short* gAL = AL + (size_t)(rowBase + ar) * HID + ch * 32;
#pragma unroll
        for (int i = 0; i < 2; i++) {
            int seg = as0 + i;
            cp_async16(s0         + ar * A_ROW_B + seg * 16, (const char*)gAH + seg * 16);
            cp_async16(s0 + 10240 + ar * A_ROW_B + seg * 16, (const char*)gAL + seg * 16);
        }
        const unsigned short* gBH = BH + (size_t)(colBase + br) * HID + ch * 32;
        const unsigned short* gBL = BL + (size_t)(colBase + br) * HID + ch * 32;
        cp_async16(s0 + 20480 + br * A_ROW_B + bs * 16, (const char*)gBH + bs * 16);
        cp_async16(s0 + 25600 + br * A_ROW_B + bs * 16, (const char*)gBL + bs * 16);
        cp_commit();
    };

    const uint32_t aoff = (uint32_t)(warpM * 32 + (lane & 15)) * A_ROW_B + ((lane >> 4) << 4);
    const uint32_t boff = (uint32_t)(warpN * 32 + (lane & 7) + ((lane >> 4) & 1) * 8) * A_ROW_B
                        + (((lane >> 3) & 1) << 4);

    issue(0, 0);
    for (int ch = 0; ch < 8; ch++) {
        if (ch < 7) { issue(ch + 1, (ch + 1) & 1); cp_wait<1>(); }
        else        { cp_wait<0>(); }
        __syncthreads();

        uint32_t s0 = sbase + (ch & 1) * STAGE_BYTES;
#pragma unroll
        for (int kh = 0; kh < 2; kh++) {
            uint32_t kadd = kh * 32;
            uint32_t Ah[2][4], Al[2][4], Bh[2][4], Bl[2][4];
            ldsm4(Ah[0], s0 + aoff + kadd);
            ldsm4(Ah[1], s0 + aoff + 16 * A_ROW_B + kadd);
            ldsm4(Al[0], s0 + 10240 + aoff + kadd);
            ldsm4(Al[1], s0 + 10240 + aoff + 16 * A_ROW_B + kadd);
            ldsm4(Bh[0], s0 + 20480 + boff + kadd);
            ldsm4(Bh[1], s0 + 20480 + boff + 16 * A_ROW_B + kadd);
            ldsm4(Bl[0], s0 + 25600 + boff + kadd);
            ldsm4(Bl[1], s0 + 25600 + boff + 16 * A_ROW_B + kadd);
#pragma unroll
            for (int mi = 0; mi < 2; mi++)
#pragma unroll
                for (int np = 0; np < 2; np++)
#pragma unroll
                    for (int hf = 0; hf < 2; hf++) {
                        float* c = acc[mi][np * 2 + hf];
                        mma16816(c, Ah[mi], Bh[np][hf * 2], Bh[np][hf * 2 + 1]);
                        mma16816(c, Ah[mi], Bl[np][hf * 2], Bl[np][hf * 2 + 1]);
                        mma16816(c, Al[mi], Bh[np][hf * 2], Bh[np][hf * 2 + 1]);
                    }
        }
        __syncthreads();
    }

    const int g = lane >> 2, tig = lane & 3;
#pragma unroll
    for (int mi = 0; mi < 2; mi++)
#pragma unroll
        for (int nf = 0; nf < 4; nf++) {
            int col = colBase + warpN * 32 + nf * 8 + tig * 2;
            float b0 = bias[col], b1 = bias[col + 1];
            int row0 = rowBase + warpM * 32 + mi * 16 + g;
            int row1 = row0 + 8;
            if (mode == 0) {
                int plane = col >> 8, cm = col & 255;
                float* base = C + (size_t)plane * PLANE + cm;
                if (row0 < NN) {
                    float2 v = make_float2(acc[mi][nf][0] + b0, acc[mi][nf][1] + b1);
                    *(float2*)(base + (size_t)row0 * HID) = v;
                }
                if (row1 < NN) {
                    float2 v = make_float2(acc[mi][nf][2] + b0, acc[mi][nf][3] + b1);
                    *(float2*)(base + (size_t)row1 * HID) = v;
                }
            } else {
                if (row0 < NN) {
                    float2 v = make_float2(fmaxf(acc[mi][nf][0] + b0, 0.f),
                                           fmaxf(acc[mi][nf][1] + b1, 0.f));
                    *(float2*)(C + (size_t)row0 * 128 + col) = v;
                }
                if (row1 < NN) {
                    float2 v = make_float2(fmaxf(acc[mi][nf][2] + b0, 0.f),
                                           fmaxf(acc[mi][nf][3] + b1, 0.f));
                    *(float2*)(C + (size_t)row1 * 128 + col) = v;
                }
            }
        }
}

// ---------------- fp32 GEMM 128x128x16 (encoder) ----------------
__global__ __launch_bounds__(256) void sgemm128(
    const float* __restrict__ A, const float* __restrict__ B,
    const float* __restrict__ bias, float* __restrict__ C,
    int M, int N, int K, int bf16out,
    unsigned short* __restrict__ AbfH, unsigned short* __restrict__ AbfL)
{
    __shared__ float As[2][16][128];
    __shared__ float Bs[2][16][128];
    const int tid = threadIdx.x;
    const int tx = tid & 15;
    const int ty = tid >> 4;
    const int rowBase = blockIdx.y * 128;
    const int colBase = blockIdx.x * 128;

    const int ar = tid >> 2;
    const int ak = (tid & 3) * 4;
    const int br = tid >> 5;
    const int bc = (tid & 31) * 4;

    float acc[8][8];
#pragma unroll
    for (int i = 0; i < 8; i++)
#pragma unroll
        for (int j = 0; j < 8; j++) acc[i][j] = 0.f;

    float4 a0v, a1v, b0v, b1v;
    {
        int row0 = rowBase + ar, row1 = rowBase + ar + 64;
        a0v = (row0 < M) ? *(const float4*)(A + (size_t)row0 * K + ak) : make_float4(0,0,0,0);
        a1v = (row1 < M) ? *(const float4*)(A + (size_t)row1 * K + ak) : make_float4(0,0,0,0);
        b0v = *(const float4*)(B + (size_t)br * N + colBase + bc);
        b1v = *(const float4*)(B + (size_t)(br + 8) * N + colBase + bc);
    }
    As[0][ak+0][ar] = a0v.x; As[0][ak+1][ar] = a0v.y; As[0][ak+2][ar] = a0v.z; As[0][ak+3][ar] = a0v.w;
    As[0][ak+0][ar+64] = a1v.x; As[0][ak+1][ar+64] = a1v.y; As[0][ak+2][ar+64] = a1v.z; As[0][ak+3][ar+64] = a1v.w;
    *(float4*)&Bs[0][br][bc] = b0v;
    *(float4*)&Bs[0][br+8][bc] = b1v;
    __syncthreads();

    int buf = 0;
    for (int k0 = 16; k0 < K; k0 += 16) {
        {
            int row0 = rowBase + ar, row1 = rowBase + ar + 64;
            a0v = (row0 < M) ? *(const float4*)(A + (size_t)row0 * K + k0 + ak) : make_float4(0,0,0,0);
            a1v = (row1 < M) ? *(const float4*)(A + (size_t)row1 * K + k0 + ak) : make_float4(0,0,0,0);
            b0v = *(const float4*)(B + (size_t)(k0 + br) * N + colBase + bc);
            b1v = *(const float4*)(B + (size_t)(k0 + br + 8) * N + colBase + bc);
        }
#pragma unroll
        for (int kk = 0; kk < 16; kk++) {
            float4 xa0 = *(float4*)&As[buf][kk][ty * 8];
            float4 xa1 = *(float4*)&As[buf][kk][ty * 8 + 4];
            float4 xb0 = *(float4*)&Bs[buf][kk][tx * 8];
            float4 xb1 = *(float4*)&Bs[buf][kk][tx * 8 + 4];
            float a[8] = {xa0.x, xa0.y, xa0.z, xa0.w, xa1.x, xa1.y, xa1.z, xa1.w};
            float b[8] = {xb0.x, xb0.y, xb0.z, xb0.w, xb1.x, xb1.y, xb1.z, xb1.w};
#pragma unroll
            for (int i = 0; i < 8; i++)
#pragma unroll
                for (int j = 0; j < 8; j++)
                    acc[i][j] = fmaf(a[i], b[j], acc[i][j]);
        }
        int nb = buf ^ 1;
        As[nb][ak+0][ar] = a0v.x; As[nb][ak+1][ar] = a0v.y; As[nb][ak+2][ar] = a0v.z; As[nb][ak+3][ar] = a0v.w;
        As[nb][ak+0][ar+64] = a1v.x; As[nb][ak+1][ar+64] = a1v.y; As[nb][ak+2][ar+64] = a1v.z; As[nb][ak+3][ar+64] = a1v.w;
        *(float4*)&Bs[nb][br][bc] = b0v;
        *(float4*)&Bs[nb][br+8][bc] = b1v;
        __syncthreads();
        buf = nb;
    }
#pragma unroll
    for (int kk = 0; kk < 16; kk++) {
        float4 xa0 = *(float4*)&As[buf][kk][ty * 8];
        float4 xa1 = *(float4*)&As[buf][kk][ty * 8 + 4];
        float4 xb0 = *(float4*)&Bs[buf][kk][tx * 8];
        float4 xb1 = *(float4*)&Bs[buf][kk][tx * 8 + 4];
        float a[8] = {xa0.x, xa0.y, xa0.z, xa0.w, xa1.x, xa1.y, xa1.z, xa1.w};
        float b[8] = {xb0.x, xb0.y, xb0.z, xb0.w, xb1.x, xb1.y, xb1.z, xb1.w};
#pragma unroll
        for (int i = 0; i < 8; i++)
#pragma unroll
            for (int j = 0; j < 8; j++)
                acc[i][j] = fmaf(a[i], b[j], acc[i][j]);
    }

#pragma unroll
    for (int i = 0; i < 8; i++) {
        int row = rowBase + ty * 8 + i;
        if (row >= M) continue;
#pragma unroll
        for (int j4 = 0; j4 < 2; j4++) {
            int col = colBase + tx * 8 + j4 * 4;
            float4 v = make_float4(acc[i][j4*4+0], acc[i][j4*4+1], acc[i][j4*4+2], acc[i][j4*4+3]);
            if (bias) {
                float4 bb = *(const float4*)(bias + col);
                v.x += bb.x; v.y += bb.y; v.z += bb.z; v.w += bb.w;
            }
            *(float4*)(C + (size_t)row * N + col) = v;
            if (bf16out) {
                size_t off = (size_t)row * HID + col;
                unsigned short h0 = bf16_bits(v.x), h1 = bf16_bits(v.y);
                unsigned short h2 = bf16_bits(v.z), h3 = bf16_bits(v.w);
                uint2 hw;
                hw.x = (uint32_t)h0 | ((uint32_t)h1 << 16);
                hw.y = (uint32_t)h2 | ((uint32_t)h3 << 16);
                *(uint2*)(AbfH + off) = hw;
                unsigned short l0 = bf16_bits(v.x - bf16_round(v.x));
                unsigned short l1 = bf16_bits(v.y - bf16_round(v.y));
                unsigned short l2 = bf16_bits(v.z - bf16_round(v.z));
                unsigned short l3 = bf16_bits(v.w - bf16_round(v.w));
                uint2 lw;
                lw.x = (uint32_t)l0 | ((uint32_t)l1 << 16);
                lw.y = (uint32_t)l2 | ((uint32_t)l3 << 16);
                *(uint2*)(AbfL + off) = lw;
            }
        }
    }
}

// ---------------- ONE merged prep kernel (keeps launch count low for ncu) ----------------
// sections by blockIdx.x; 256 threads each
__global__ void prep_kernel(
    const float* __restrict__ Wq, const float* __restrict__ Wk,
    const float* __restrict__ Wv, const float* __restrict__ Wsk,
    const float* __restrict__ bq, const float* __restrict__ bk,
    const float* __restrict__ bv, const float* __restrict__ bsk,
    const float* __restrict__ enc_We, const float* __restrict__ enc_be,
    const float* __restrict__ We, const float* __restrict__ cp_W1,
    unsigned short* __restrict__ WtH, unsigned short* __restrict__ WtL,
    unsigned short* __restrict__ Wt1H, unsigned short* __restrict__ Wt1L,
    float* __restrict__ bpack, float* __restrict__ Wc, float* __restrict__ WcT,
    float* __restrict__ bcomb,
    unsigned short* __restrict__ AH, unsigned short* __restrict__ AL,
    int* __restrict__ counts, int* __restrict__ cursor)
{
    int b = blockIdx.x;
    int t = threadIdx.x;
    if (b < 4096) {                       // pack_wt: LL*1024*256
        int idx = b * 256 + t;
        int k = idx & 255;
        int rem = idx >> 8;
        int j = rem & 1023;
        int l = rem >> 10;
        int sel = j >> 8, jj = j & 255;
        const float* W = (sel == 0) ? Wq : (sel == 1) ? Wk : (sel == 2) ? Wv : Wsk;
        float w = W[((size_t)l * HID + k) * HID + jj];
        size_t off = ((size_t)l * 1024 + j) * HID + k;
        WtH[off] = bf16_bits(w);
        WtL[off] = bf16_bits(w - bf16_round(w));
    } else if (b < 4224) {                // pack cp_W1^T: 128*256
        int idx = (b - 4096) * 256 + t;
        int k = idx & 255, n = idx >> 8;
        float w = cp_W1[(size_t)k * 128 + n];
        Wt1H[idx] = bf16_bits(w);
        Wt1L[idx] = bf16_bits(w - bf16_round(w));
    } else if (b < 4480) {                // wcomb: (l,f) = 256 blocks
        int lf = b - 4224;
        int l = lf >> 6, f = lf & 63;
        const float* Wl = We + (size_t)l * HID * HID;
        const float* er = enc_We + (size_t)f * HID;
        float s = 0.f;
        for (int k = 0; k < HID; k++) s = fmaf(er[k], Wl[(size_t)k * HID + t], s);
        Wc [((size_t)l * EFD + f) * HID + t] = s;
        WcT[((size_t)l * HID + t) * EFD + f] = s;
    } else if (b < 4484) {                // bcomb: 4 blocks
        int l = b - 4480;
        const float* Wl = We + (size_t)l * HID * HID;
        float s = 0.f;
        for (int k = 0; k < HID; k++) s = fmaf(enc_be[k], Wl[(size_t)k * HID + t], s);
        bcomb[l * HID + t] = s;
    } else if (b < 4500) {                // pack_b: LL*1024
        int i = (b - 4484) * 256 + t;
        int j = i & 1023, l = i >> 10;
        int sel = j >> 8, jj = j & 255;
        const float* B = (sel == 0) ? bq : (sel == 1) ? bk : (sel == 2) ? bv : bsk;
        bpack[i] = B[l * HID + jj];
    } else if (b < 4580) {                // zero pad rows of Abf
        int idx = (b - 4500) * 256 + t;
        size_t off = (size_t)NN * HID + idx;
        AH[off] = 0;
        AL[off] = 0;
    } else {                              // zero counts + cursor
        int i = (b - 4580) * 256 + t;
        if (i < NN) { counts[i] = 0; cursor[i] = 0; }
    }
}
#define PREP_BLOCKS (4580 + (NN + 255) / 256)

// ---------------- CSR build ----------------
__global__ void hist_kernel(const int* __restrict__ dst, int* __restrict__ counts) {
    int e = blockIdx.x * 256 + threadIdx.x;
    if (e < EE) atomicAdd(&counts[dst[e]], 1);
}
__global__ void scan_kernel(const int* __restrict__ counts, int* __restrict__ rowptr, int n) {
    __shared__ int sh[1024];
    __shared__ int carry;
    if (threadIdx.x == 0) carry = 0;
    __syncthreads();
    for (int base = 0; base < n; base += 1024) {
        int i = base + threadIdx.x;
        int v = (i < n) ? counts[i] : 0;
        sh[threadIdx.x] = v;
        __syncthreads();
        for (int off = 1; off < 1024; off <<= 1) {
            int t = (threadIdx.x >= off) ? sh[threadIdx.x - off] : 0;
            __syncthreads();
            sh[threadIdx.x] += t;
            __syncthreads();
        }
        if (i < n) rowptr[i + 1] = carry + sh[threadIdx.x];
        __syncthreads();
        if (threadIdx.x == 1023) carry += sh[1023];
        __syncthreads();
    }
    if (threadIdx.x == 0) rowptr[0] = 0;
}
__global__ void scatter_kernel(const int* __restrict__ dst, const int* __restrict__ rowptr,
                               int* __restrict__ cursor, int* __restrict__ perm) {
    int e = blockIdx.x * 256 + threadIdx.x;
    if (e >= EE) return;
    int d = dst[e];
    int pos = rowptr[d] + atomicAdd(&cursor[d], 1);
    perm[pos] = e;
}

// ---------------- fused attention + residual + LN + bf16 conversion ----------------
__global__ __launch_bounds__(256) void attn_kernel(
    const float* __restrict__ QKVS, const float* __restrict__ edge_attr,
    const float* __restrict__ Wcomb, const float* __restrict__ WcombT,
    const float* __restrict__ bcomb,
    const int* __restrict__ src, const int* __restrict__ perm,
    const int* __restrict__ rowptr,
    float* __restrict__ h, const float* __restrict__ lng, const float* __restrict__ lnb,
    unsigned short* __restrict__ AbfH, unsigned short* __restrict__ AbfL,
    float* __restrict__ out_h)
{
    __shared__ int   sh_s[TILE];
    __shared__ float sh_ea[TILE * EFD];
    __shared__ float red[8];

    const int n    = blockIdx.x;
    const int warp = threadIdx.x >> 5;
    const int lane = threadIdx.x & 31;
    const int col  = warp * DD + lane;
    const int beg = rowptr[n], end = rowptr[n + 1];
    const float* Kpl = QKVS + PLANE;
    const float* Vpl = QKVS + 2 * PLANE;
    const float q = QKVS[(size_t)n * HID + col];
    const int hb = warp * DD;

    float qw0 = 0.f, qw1 = 0.f;
#pragma unroll
    for (int d = 0; d < 32; d++) {
        float qd = __shfl_sync(0xffffffffu, q, d);
        qw0 = fmaf(qd, WcombT[(size_t)(hb + d) * EFD + lane], qw0);
        qw1 = fmaf(qd, WcombT[(size_t)(hb + d) * EFD + 32 + lane], qw1);
    }

    float m = -3.0e38f, s = 0.f, acc = 0.f, wea0 = 0.f, wea1 = 0.f;
    const float inv_sqrt_d = 0.17677669529663687f;

    for (int base = beg; base < end; base += TILE) {
        int cnt = min(TILE, end - base);
        __syncthreads();
        for (int t = threadIdx.x; t < cnt; t += 256)
            sh_s[t] = src[perm[base + t]];
        __syncthreads();
        for (int t = threadIdx.x; t < cnt * 16; t += 256) {
            int j = t >> 4, p4 = (t & 15) * 4;
            *(float4*)&sh_ea[j * EFD + p4] =
                *(const float4*)(edge_attr + (size_t)perm[base + j] * EFD + p4);
        }
        __syncthreads();

        int j = 0;
        for (; j + 8 <= cnt; j += 8) {
            float ea0[8], ea1[8], kk[8], vv[8], sc[8];
#pragma unroll
            for (int i = 0; i < 8; i++) {
                int sn = sh_s[j + i];
                ea0[i] = sh_ea[(j + i) * EFD + lane];
                ea1[i] = sh_ea[(j + i) * EFD + 32 + lane];
                kk[i]  = Kpl[(size_t)sn * HID + col];
                vv[i]  = Vpl[(size_t)sn * HID + col];
            }
#pragma unroll
            for (int i = 0; i < 8; i++)
                sc[i] = fmaf(q, kk[i], fmaf(qw0, ea0[i], qw1 * ea1[i]));
#pragma unroll
            for (int i = 0; i < 8; i++)
                sc[i] = warp_sum(sc[i]) * inv_sqrt_d;

            float mx01 = fmaxf(sc[0], sc[1]), mx23 = fmaxf(sc[2], sc[3]);
            float mx45 = fmaxf(sc[4], sc[5]), mx67 = fmaxf(sc[6], sc[7]);
            float mn = fmaxf(m, fmaxf(fmaxf(mx01, mx23), fmaxf(mx45, mx67)));
            float scale = __expf(m - mn);
            float p[8];
#pragma unroll
            for (int i = 0; i < 8; i++) p[i] = __expf(sc[i] - mn);
            float ps = ((p[0]+p[1])+(p[2]+p[3])) + ((p[4]+p[5])+(p[6]+p[7]));
            float av = fmaf(p[0], vv[0], fmaf(p[1], vv[1], fmaf(p[2], vv[2], p[3]*vv[3])));
            av = fmaf(p[4], vv[4], fmaf(p[5], vv[5], fmaf(p[6], vv[6], fmaf(p[7], vv[7], av))));
            float w0 = fmaf(p[0], ea0[0], fmaf(p[1], ea0[1], fmaf(p[2], ea0[2], p[3]*ea0[3])));
            w0 = fmaf(p[4], ea0[4], fmaf(p[5], ea0[5], fmaf(p[6], ea0[6], fmaf(p[7], ea0[7], w0))));
            float w1 = fmaf(p[0], ea1[0], fmaf(p[1], ea1[1], fmaf(p[2], ea1[2], p[3]*ea1[3])));
            w1 = fmaf(p[4], ea1[4], fmaf(p[5], ea1[5], fmaf(p[6], ea1[6], fmaf(p[7], ea1[7], w1))));
            s    = fmaf(s,    scale, ps);
            acc  = fmaf(acc,  scale, av);
            wea0 = fmaf(wea0, scale, w0);
            wea1 = fmaf(wea1, scale, w1);
            m = mn;
        }
        for (; j < cnt; j++) {
            int sn = sh_s[j];
            float ea0 = sh_ea[j * EFD + lane];
            float ea1 = sh_ea[j * EFD + 32 + lane];
            float kk = Kpl[(size_t)sn * HID + col];
            float vv = Vpl[(size_t)sn * HID + col];
            float part = fmaf(q, kk, fmaf(qw0, ea0, qw1 * ea1));
            float sc = warp_sum(part) * inv_sqrt_d;
            float mn = fmaxf(m, sc);
            float scale = __expf(m - mn);
            float p     = __expf(sc - mn);
            s    = fmaf(s,    scale, p);
            acc  = fmaf(acc,  scale, p * vv);
            wea0 = fmaf(wea0, scale, p * ea0);
            wea1 = fmaf(wea1, scale, p * ea1);
            m = mn;
        }
    }

    float kec = 0.f;
#pragma unroll
    for (int f = 0; f < 32; f++) {
        float w0 = __shfl_sync(0xffffffffu, wea0, f);
        float w1 = __shfl_sync(0xffffffffu, wea1, f);
        kec = fmaf(w0, Wcomb[(size_t)f * HID + col], kec);
        kec = fmaf(w1, Wcomb[(size_t)(f + 32) * HID + col], kec);
    }
    float res = (acc + kec + s * bcomb[col]) / (s + 1e-16f);

    const float* SKpl = QKVS + 3 * PLANE;
    size_t idx = (size_t)n * HID + col;
    float v = h[idx] + res + SKpl[idx];

    __syncthreads();
    float ws = warp_sum(v);
    if (lane == 0) red[warp] = ws;
    __syncthreads();
    float mean = 0.f;
#pragma unroll
    for (int w = 0; w < 8; w++) mean += red[w];
    mean *= (1.0f / HID);
    __syncthreads();
    float dv = v - mean;
    float ws2 = warp_sum(dv * dv);
    if (lane == 0) red[warp] = ws2;
    __syncthreads();
    float var = 0.f;
#pragma unroll
    for (int w = 0; w < 8; w++) var += red[w];
    var *= (1.0f / HID);
    float o = dv * rsqrtf(var + 1e-5f) * lng[col] + lnb[col];
    h[idx] = o;
    if (out_h) out_h[idx] = o;

    AbfH[idx] = bf16_bits(o);
    AbfL[idx] = bf16_bits(o - bf16_round(o));
}

// ---------------- outputs ----------------
__global__ void zero_g_kernel(float* __restrict__ out) {
    out[OFF_G + threadIdx.x] = 0.f;
}
__global__ void mean_pool_kernel(const float* __restrict__ h, float* __restrict__ out) {
    int per = (NN + gridDim.x - 1) / gridDim.x;
    int r0 = blockIdx.x * per, r1 = min(NN, r0 + per);
    float s = 0.f;
    for (int r = r0; r < r1; r++) s += h[(size_t)r * HID + threadIdx.x];
    atomicAdd(&out[OFF_G + threadIdx.x], s * (1.0f / NN));
}
__global__ __launch_bounds__(256) void contagion_kernel(
    const float* __restrict__ T1, const float* __restrict__ W2,
    const float* __restrict__ b2, float* __restrict__ out)
{
    int n = blockIdx.x * 8 + (threadIdx.x >> 5);
    if (n >= NN) return;
    int lane = threadIdx.x & 31;
    float s = 0.f;
#pragma unroll
    for (int i = 0; i < 4; i++) {
        int c = lane + 32 * i;
        s = fmaf(T1[(size_t)n * 128 + c], W2[c], s);
    }
    s = warp_sum(s);
    if (lane == 0) out[OFF_C + n] = 1.f / (1.f + expf(-(s + b2[0])));
}
__global__ void systemic_kernel(const float* __restrict__ W1, const float* __restrict__ b1,
                                const float* __restrict__ W2, const float* __restrict__ b2,
                                float* __restrict__ out)
{
    __shared__ float sh[128];
    int j = threadIdx.x;
    const float* g = out + OFF_G;
    float t = b1[j];
    for (int k = 0; k < HID; k++) t = fmaf(g[k], W1[k * 128 + j], t);
    sh[j] = fmaxf(t, 0.f) * W2[j];
    __syncthreads();
    for (int off = 64; off > 0; off >>= 1) {
        if (j < off) sh[j] += sh[j + off];
        __syncthreads();
    }
    if (j == 0) out[OFF_S] = 1.f / (1.f + expf(-(sh[0] + b2[0])));
}

// ---------------- host ----------------
static inline void* sym(const void* s) { void* p = nullptr; cudaGetSymbolAddress(&p, s); return p; }

extern "C" void kernel_launch(void* const* d_in, const int* in_sizes, int n_in,
                              void* d_out, int out_size)
{
    const float* x         = (const float*)d_in[0];
    const float* edge_attr = (const float*)d_in[1];
    const int*   edge_index= (const int*)  d_in[2];
    const float* enc_Wn = (const float*)d_in[3];
    const float* enc_bn = (const float*)d_in[4];
    const float* enc_We = (const float*)d_in[5];
    const float* enc_be = (const float*)d_in[6];
    const float* Wq = (const float*)d_in[7];  const float* bq = (const float*)d_in[8];
    const float* Wk = (const float*)d_in[9];  const float* bk = (const float*)d_in[10];
    const float* Wv = (const float*)d_in[11]; const float* bv = (const float*)d_in[12];
    const float* We = (const float*)d_in[13];
    const float* Wsk= (const float*)d_in[14]; const float* bsk= (const float*)d_in[15];
    const float* ln_g = (const float*)d_in[16];
    const float* ln_b = (const float*)d_in[17];
    const float* cp_W1 = (const float*)d_in[18]; const float* cp_b1 = (const float*)d_in[19];
    const float* cp_W2 = (const float*)d_in[20]; const float* cp_b2 = (const float*)d_in[21];
    const float* sp_W1 = (const float*)d_in[22]; const float* sp_b1 = (const float*)d_in[23];
    const float* sp_W2 = (const float*)d_in[24]; const float* sp_b2 = (const float*)d_in[25];
    float* out = (float*)d_out;

    float* h    = (float*)sym(d_h);
    float* QKVS = (float*)sym(d_QKVS);
    unsigned short* AbfH = (unsigned short*)sym(d_AbfH);
    unsigned short* AbfL = (unsigned short*)sym(d_AbfL);
    unsigned short* WtH  = (unsigned short*)sym(d_WtH);
    unsigned short* WtL  = (unsigned short*)sym(d_WtL);
    unsigned short* Wt1H = (unsigned short*)sym(d_Wt1H);
    unsigned short* Wt1L = (unsigned short*)sym(d_Wt1L);
    float* bpack= (float*)sym(d_bpack);
    float* Wcomb= (float*)sym(d_Wcomb);
    float* WcombT=(float*)sym(d_WcombT);
    float* bcomb= (float*)sym(d_bcomb);
    float* T1   = (float*)sym(d_T1);
    int* counts = (int*)sym(d_counts);
    int* cursor = (int*)sym(d_cursor);
    int* rowptr = (int*)sym(d_rowptr);
    int* perm   = (int*)sym(d_perm);

    const int* src = edge_index;
    const int* dst = edge_index + EE;

    cudaFuncSetAttribute(hgemm_kernel, cudaFuncAttributeMaxDynamicSharedMemorySize,
                         2 * STAGE_BYTES);

    // launch 0: all prep (packs + wcomb + bcomb + pads + CSR zero)
    prep_kernel<<<PREP_BLOCKS, 256>>>(Wq, Wk, Wv, Wsk, bq, bk, bv, bsk,
                                      enc_We, enc_be, We, cp_W1,
                                      WtH, WtL, Wt1H, Wt1L, bpack, Wcomb, WcombT, bcomb,
                                      AbfH, AbfL, counts, cursor);

    // launch 1: node encoder (fp32 GEMM, writes h + bf16 split)
    {
        dim3 g(HID / 128, (NN + 127) / 128);
        sgemm128<<<g, 256>>>(x, enc_Wn, enc_bn, h, NN, HID, NFD, 1, AbfH, AbfL);
    }

    // launches 2-4: CSR build (by dst)
    hist_kernel<<<(EE + 255) / 256, 256>>>(dst, counts);
    scan_kernel<<<1, 1024>>>(counts, rowptr, NN);
    scatter_kernel<<<(EE + 255) / 256, 256>>>(dst, rowptr, cursor, perm);

    // launch 5: first hgemm (ncu -s 5 captures this)
    for (int l = 0; l < LL; l++) {
        {
            dim3 g(1024 / 64, NN_PAD / 128);
            hgemm_kernel<<<g, 256, 2 * STAGE_BYTES>>>(
                AbfH, AbfL,
                WtH + (size_t)l * 1024 * HID,
                WtL + (size_t)l * 1024 * HID,
                bpack + (size_t)l * 1024, QKVS, 0);
        }
        attn_kernel<<<NN, 256>>>(QKVS, edge_attr,
                                 Wcomb + (size_t)l * EFD * HID,
                                 WcombT + (size_t)l * HID * EFD,
                                 bcomb + (size_t)l * HID,
                                 src, perm, rowptr,
                                 h, ln_g, ln_b, AbfH, AbfL,
                                 (l == LL - 1) ? (out + OFF_H) : nullptr);
    }

    // outputs
    zero_g_kernel<<<1, HID>>>(out);
    mean_pool_kernel<<<128, HID>>>(h, out);
    {
        dim3 g(128 / 64, NN_PAD / 128);
        hgemm_kernel<<<g, 256, 2 * STAGE_BYTES>>>(AbfH, AbfL, Wt1H, Wt1L, cp_b1, T1, 1);
    }
    contagion_kernel<<<(NN + 7) / 8, 256>>>(T1, cp_W2, cp_b2, out);
    systemic_kernel<<<1, 128>>>(sp_W1, sp_b1, sp_W2, sp_b2, out);
}

// round 12
// speedup vs baseline: 1.1016x; 1.1016x over previous
#include <cuda_runtime.h>
#include <cuda_bf16.h>
#include <math.h>
#include <stdint.h>

#define NN     30000
#define NN_PAD 30080
#define EE     480000
#define NFD    128
#define EFD    64
#define HID    256
#define LL     4
#define NH     8
#define DD     32
#define TILE   64

#define OFF_H 0
#define OFF_G (NN*HID)
#define OFF_C (NN*HID + HID)
#define OFF_S (NN*HID + HID + NN)

#define PLANE ((size_t)NN * HID)

#define STAGE_BYTES 30720
#define A_ROW_B 80

// ---------------- static device scratch ----------------
__device__ float d_h   [NN*HID];
__device__ float d_QKVS[(size_t)4*NN*HID];   // planes: Q | K | V | SK
__device__ __align__(16) unsigned short d_AbfH[(size_t)NN_PAD*HID];
__device__ __align__(16) unsigned short d_AbfL[(size_t)NN_PAD*HID];
__device__ __align__(16) unsigned short d_WtH[(size_t)LL*1024*HID];  // [l][n][k]
__device__ __align__(16) unsigned short d_WtL[(size_t)LL*1024*HID];
__device__ __align__(16) unsigned short d_Wt1H[128*HID];             // cp_W1^T
__device__ __align__(16) unsigned short d_Wt1L[128*HID];
__device__ float d_bpack[LL*1024];
__device__ float d_Wcomb [LL*EFD*HID];
__device__ float d_WcombT[LL*HID*EFD];
__device__ float d_bcomb[LL*HID];
__device__ float d_T1[NN*(HID/2)];
__device__ int   d_counts[NN];
__device__ int   d_cursor[NN];
__device__ int   d_rowptr[NN+1];
__device__ int   d_perm[EE];

// ---------------- small helpers ----------------
__device__ __forceinline__ float warp_sum(float v) {
    v += __shfl_xor_sync(0xffffffffu, v, 16);
    v += __shfl_xor_sync(0xffffffffu, v, 8);
    v += __shfl_xor_sync(0xffffffffu, v, 4);
    v += __shfl_xor_sync(0xffffffffu, v, 2);
    v += __shfl_xor_sync(0xffffffffu, v, 1);
    return v;
}
__device__ __forceinline__ unsigned short bf16_bits(float f) {
    __nv_bfloat16 b = __float2bfloat16(f);
    return *(unsigned short*)&b;
}
__device__ __forceinline__ float bf16_round(float f) {
    return __bfloat162float(__float2bfloat16(f));
}

// ---------------- PTX wrappers (plain sm_80+ features only) ----------------
__device__ __forceinline__ void cp_async16(uint32_t saddr, const void* gptr) {
    asm volatile("cp.async.cg.shared.global [%0], [%1], 16;" :: "r"(saddr), "l"(gptr));
}
__device__ __forceinline__ void cp_commit() {
    asm volatile("cp.async.commit_group;");
}
template <int N>
__device__ __forceinline__ void cp_wait() {
    asm volatile("cp.async.wait_group %0;" :: "n"(N));
}
__device__ __forceinline__ void ldsm4(uint32_t* r, uint32_t addr) {
    asm volatile("ldmatrix.sync.aligned.m8n8.x4.shared.b16 {%0,%1,%2,%3}, [%4];"
                 : "=r"(r[0]), "=r"(r[1]), "=r"(r[2]), "=r"(r[3]) : "r"(addr));
}
__device__ __forceinline__ void mma16816(float* c, const uint32_t* a, uint32_t b0, uint32_t b1) {
    asm volatile(
        "mma.sync.aligned.m16n8k16.row.col.f32.bf16.bf16.f32 "
        "{%0,%1,%2,%3}, {%4,%5,%6,%7}, {%8,%9}, {%0,%1,%2,%3};"
        : "+f"(c[0]), "+f"(c[1]), "+f"(c[2]), "+f"(c[3])
        : "r"(a[0]), "r"(a[1]), "r"(a[2]), "r"(a[3]), "r"(b0), "r"(b1));
}

// ---------------- tensor-core GEMM (bf16 hi/lo split, fp32 acc) ----------------
// mode 0: C = QKVS planes; logical [NN_PAD][1024] = A[.,256] @ Wt[1024][256]^T + bias
// mode 1: C = T1 [NN][128] = relu(A @ Wt1^T + bias)
__global__ __launch_bounds__(256) void hgemm_kernel(
    const unsigned short* __restrict__ AH, const unsigned short* __restrict__ AL,
    const unsigned short* __restrict__ BH, const unsigned short* __restrict__ BL,
    const float* __restrict__ bias, float* __restrict__ C, int mode)
{
    extern __shared__ unsigned char sm[];
    uint32_t sbase = (uint32_t)__cvta_generic_to_shared(sm);
    const int tid  = threadIdx.x;
    const int wid  = tid >> 5, lane = tid & 31;
    const int warpM = wid & 3, warpN = wid >> 2;
    const int rowBase = blockIdx.y * 128;
    const int colBase = blockIdx.x * 64;

    float acc[2][4][4];
#pragma unroll
    for (int mi = 0; mi < 2; mi++)
#pragma unroll
        for (int nf = 0; nf < 4; nf++)
#pragma unroll
            for (int k = 0; k < 4; k++) acc[mi][nf][k] = 0.f;

    const int ar  = tid >> 1;
    const int as0 = (tid & 1) * 2;
    const int br  = tid >> 2;
    const int bs  = tid & 3;

    auto issue = [&](int ch, int stage) {
        uint32_t s0 = sbase + stage * STAGE_BYTES;
        const unsigned short* gAH = AH + (size_t)(rowBase + ar) * HID + ch * 32;
        const unsigned short* gAL = AL + (size_t)(rowBase + ar) * HID + ch * 32;
#pragma unroll
        for (int i = 0; i < 2; i++) {
            int seg = as0 + i;
            cp_async16(s0         + ar * A_ROW_B + seg * 16, (const char*)gAH + seg * 16);
            cp_async16(s0 + 10240 + ar * A_ROW_B + seg * 16, (const char*)gAL + seg * 16);
        }
        const unsigned short* gBH = BH + (size_t)(colBase + br) * HID + ch * 32;
        const unsigned short* gBL = BL + (size_t)(colBase + br) * HID + ch * 32;
        cp_async16(s0 + 20480 + br * A_ROW_B + bs * 16, (const char*)gBH + bs * 16);
        cp_async16(s0 + 25600 + br * A_ROW_B + bs * 16, (const char*)gBL + bs * 16);
        cp_commit();
    };

    const uint32_t aoff = (uint32_t)(warpM * 32 + (lane & 15)) * A_ROW_B + ((lane >> 4) << 4);
    const uint32_t boff = (uint32_t)(warpN * 32 + (lane & 7) + ((lane >> 4) & 1) * 8) * A_ROW_B
                        + (((lane >> 3) & 1) << 4);

    issue(0, 0);
    for (int ch = 0; ch < 8; ch++) {
        if (ch < 7) { issue(ch + 1, (ch + 1) & 1); cp_wait<1>(); }
        else        { cp_wait<0>(); }
        __syncthreads();

        uint32_t s0 = sbase + (ch & 1) * STAGE_BYTES;
#pragma unroll
        for (int kh = 0; kh < 2; kh++) {
            uint32_t kadd = kh * 32;
            uint32_t Ah[2][4], Al[2][4], Bh[2][4], Bl[2][4];
            ldsm4(Ah[0], s0 + aoff + kadd);
            ldsm4(Ah[1], s0 + aoff + 16 * A_ROW_B + kadd);
            ldsm4(Al[0], s0 + 10240 + aoff + kadd);
            ldsm4(Al[1], s0 + 10240 + aoff + 16 * A_ROW_B + kadd);
            ldsm4(Bh[0], s0 + 20480 + boff + kadd);
            ldsm4(Bh[1], s0 + 20480 + boff + 16 * A_ROW_B + kadd);
            ldsm4(Bl[0], s0 + 25600 + boff + kadd);
            ldsm4(Bl[1], s0 + 25600 + boff + 16 * A_ROW_B + kadd);
#pragma unroll
            for (int mi = 0; mi < 2; mi++)
#pragma unroll
                for (int np = 0; np < 2; np++)
#pragma unroll
                    for (int hf = 0; hf < 2; hf++) {
                        float* c = acc[mi][np * 2 + hf];
                        mma16816(c, Ah[mi], Bh[np][hf * 2], Bh[np][hf * 2 + 1]);
                        mma16816(c, Ah[mi], Bl[np][hf * 2], Bl[np][hf * 2 + 1]);
                        mma16816(c, Al[mi], Bh[np][hf * 2], Bh[np][hf * 2 + 1]);
                    }
        }
        __syncthreads();
    }

    const int g = lane >> 2, tig = lane & 3;
#pragma unroll
    for (int mi = 0; mi < 2; mi++)
#pragma unroll
        for (int nf = 0; nf < 4; nf++) {
            int col = colBase + warpN * 32 + nf * 8 + tig * 2;
            float b0 = bias[col], b1 = bias[col + 1];
            int row0 = rowBase + warpM * 32 + mi * 16 + g;
            int row1 = row0 + 8;
            if (mode == 0) {
                int plane = col >> 8, cm = col & 255;
                float* base = C + (size_t)plane * PLANE + cm;
                if (row0 < NN) {
                    float2 v = make_float2(acc[mi][nf][0] + b0, acc[mi][nf][1] + b1);
                    *(float2*)(base + (size_t)row0 * HID) = v;
                }
                if (row1 < NN) {
                    float2 v = make_float2(acc[mi][nf][2] + b0, acc[mi][nf][3] + b1);
                    *(float2*)(base + (size_t)row1 * HID) = v;
                }
            } else {
                if (row0 < NN) {
                    float2 v = make_float2(fmaxf(acc[mi][nf][0] + b0, 0.f),
                                           fmaxf(acc[mi][nf][1] + b1, 0.f));
                    *(float2*)(C + (size_t)row0 * 128 + col) = v;
                }
                if (row1 < NN) {
                    float2 v = make_float2(fmaxf(acc[mi][nf][2] + b0, 0.f),
                                           fmaxf(acc[mi][nf][3] + b1, 0.f));
                    *(float2*)(C + (size_t)row1 * 128 + col) = v;
                }
            }
        }
}

// ---------------- fp32 GEMM 128x128x16 (encoder) ----------------
__global__ __launch_bounds__(256) void sgemm128(
    const float* __restrict__ A, const float* __restrict__ B,
    const float* __restrict__ bias, float* __restrict__ C,
    int M, int N, int K, int bf16out,
    unsigned short* __restrict__ AbfH, unsigned short* __restrict__ AbfL)
{
    __shared__ float As[2][16][128];
    __shared__ float Bs[2][16][128];
    const int tid = threadIdx.x;
    const int tx = tid & 15;
    const int ty = tid >> 4;
    const int rowBase = blockIdx.y * 128;
    const int colBase = blockIdx.x * 128;

    const int ar = tid >> 2;
    const int ak = (tid & 3) * 4;
    const int br = tid >> 5;
    const int bc = (tid & 31) * 4;

    float acc[8][8];
#pragma unroll
    for (int i = 0; i < 8; i++)
#pragma unroll
        for (int j = 0; j < 8; j++) acc[i][j] = 0.f;

    float4 a0v, a1v, b0v, b1v;
    {
        int row0 = rowBase + ar, row1 = rowBase + ar + 64;
        a0v = (row0 < M) ? *(const float4*)(A + (size_t)row0 * K + ak) : make_float4(0,0,0,0);
        a1v = (row1 < M) ? *(const float4*)(A + (size_t)row1 * K + ak) : make_float4(0,0,0,0);
        b0v = *(const float4*)(B + (size_t)br * N + colBase + bc);
        b1v = *(const float4*)(B + (size_t)(br + 8) * N + colBase + bc);
    }
    As[0][ak+0][ar] = a0v.x; As[0][ak+1][ar] = a0v.y; As[0][ak+2][ar] = a0v.z; As[0][ak+3][ar] = a0v.w;
    As[0][ak+0][ar+64] = a1v.x; As[0][ak+1][ar+64] = a1v.y; As[0][ak+2][ar+64] = a1v.z; As[0][ak+3][ar+64] = a1v.w;
    *(float4*)&Bs[0][br][bc] = b0v;
    *(float4*)&Bs[0][br+8][bc] = b1v;
    __syncthreads();

    int buf = 0;
    for (int k0 = 16; k0 < K; k0 += 16) {
        {
            int row0 = rowBase + ar, row1 = rowBase + ar + 64;
            a0v = (row0 < M) ? *(const float4*)(A + (size_t)row0 * K + k0 + ak) : make_float4(0,0,0,0);
            a1v = (row1 < M) ? *(const float4*)(A + (size_t)row1 * K + k0 + ak) : make_float4(0,0,0,0);
            b0v = *(const float4*)(B + (size_t)(k0 + br) * N + colBase + bc);
            b1v = *(const float4*)(B + (size_t)(k0 + br + 8) * N + colBase + bc);
        }
#pragma unroll
        for (int kk = 0; kk < 16; kk++) {
            float4 xa0 = *(float4*)&As[buf][kk][ty * 8];
            float4 xa1 = *(float4*)&As[buf][kk][ty * 8 + 4];
            float4 xb0 = *(float4*)&Bs[buf][kk][tx * 8];
            float4 xb1 = *(float4*)&Bs[buf][kk][tx * 8 + 4];
            float a[8] = {xa0.x, xa0.y, xa0.z, xa0.w, xa1.x, xa1.y, xa1.z, xa1.w};
            float b[8] = {xb0.x, xb0.y, xb0.z, xb0.w, xb1.x, xb1.y, xb1.z, xb1.w};
#pragma unroll
            for (int i = 0; i < 8; i++)
#pragma unroll
                for (int j = 0; j < 8; j++)
                    acc[i][j] = fmaf(a[i], b[j], acc[i][j]);
        }
        int nb = buf ^ 1;
        As[nb][ak+0][ar] = a0v.x; As[nb][ak+1][ar] = a0v.y; As[nb][ak+2][ar] = a0v.z; As[nb][ak+3][ar] = a0v.w;
        As[nb][ak+0][ar+64] = a1v.x; As[nb][ak+1][ar+64] = a1v.y; As[nb][ak+2][ar+64] = a1v.z; As[nb][ak+3][ar+64] = a1v.w;
        *(float4*)&Bs[nb][br][bc] = b0v;
        *(float4*)&Bs[nb][br+8][bc] = b1v;
        __syncthreads();
        buf = nb;
    }
#pragma unroll
    for (int kk = 0; kk < 16; kk++) {
        float4 xa0 = *(float4*)&As[buf][kk][ty * 8];
        float4 xa1 = *(float4*)&As[buf][kk][ty * 8 + 4];
        float4 xb0 = *(float4*)&Bs[buf][kk][tx * 8];
        float4 xb1 = *(float4*)&Bs[buf][kk][tx * 8 + 4];
        float a[8] = {xa0.x, xa0.y, xa0.z, xa0.w, xa1.x, xa1.y, xa1.z, xa1.w};
        float b[8] = {xb0.x, xb0.y, xb0.z, xb0.w, xb1.x, xb1.y, xb1.z, xb1.w};
#pragma unroll
        for (int i = 0; i < 8; i++)
#pragma unroll
            for (int j = 0; j < 8; j++)
                acc[i][j] = fmaf(a[i], b[j], acc[i][j]);
    }

#pragma unroll
    for (int i = 0; i < 8; i++) {
        int row = rowBase + ty * 8 + i;
        if (row >= M) continue;
#pragma unroll
        for (int j4 = 0; j4 < 2; j4++) {
            int col = colBase + tx * 8 + j4 * 4;
            float4 v = make_float4(acc[i][j4*4+0], acc[i][j4*4+1], acc[i][j4*4+2], acc[i][j4*4+3]);
            if (bias) {
                float4 bb = *(const float4*)(bias + col);
                v.x += bb.x; v.y += bb.y; v.z += bb.z; v.w += bb.w;
            }
            *(float4*)(C + (size_t)row * N + col) = v;
            if (bf16out) {
                size_t off = (size_t)row * HID + col;
                unsigned short h0 = bf16_bits(v.x), h1 = bf16_bits(v.y);
                unsigned short h2 = bf16_bits(v.z), h3 = bf16_bits(v.w);
                uint2 hw;
                hw.x = (uint32_t)h0 | ((uint32_t)h1 << 16);
                hw.y = (uint32_t)h2 | ((uint32_t)h3 << 16);
                *(uint2*)(AbfH + off) = hw;
                unsigned short l0 = bf16_bits(v.x - bf16_round(v.x));
                unsigned short l1 = bf16_bits(v.y - bf16_round(v.y));
                unsigned short l2 = bf16_bits(v.z - bf16_round(v.z));
                unsigned short l3 = bf16_bits(v.w - bf16_round(v.w));
                uint2 lw;
                lw.x = (uint32_t)l0 | ((uint32_t)l1 << 16);
                lw.y = (uint32_t)l2 | ((uint32_t)l3 << 16);
                *(uint2*)(AbfL + off) = lw;
            }
        }
    }
}

// ---------------- ONE merged prep kernel ----------------
__global__ void prep_kernel(
    const float* __restrict__ Wq, const float* __restrict__ Wk,
    const float* __restrict__ Wv, const float* __restrict__ Wsk,
    const float* __restrict__ bq, const float* __restrict__ bk,
    const float* __restrict__ bv, const float* __restrict__ bsk,
    const float* __restrict__ enc_We, const float* __restrict__ enc_be,
    const float* __restrict__ We, const float* __restrict__ cp_W1,
    unsigned short* __restrict__ WtH, unsigned short* __restrict__ WtL,
    unsigned short* __restrict__ Wt1H, unsigned short* __restrict__ Wt1L,
    float* __restrict__ bpack, float* __restrict__ Wc, float* __restrict__ WcT,
    float* __restrict__ bcomb,
    unsigned short* __restrict__ AH, unsigned short* __restrict__ AL,
    int* __restrict__ counts, int* __restrict__ cursor)
{
    int b = blockIdx.x;
    int t = threadIdx.x;
    if (b < 4096) {                       // pack_wt: LL*1024*256
        int idx = b * 256 + t;
        int k = idx & 255;
        int rem = idx >> 8;
        int j = rem & 1023;
        int l = rem >> 10;
        int sel = j >> 8, jj = j & 255;
        const float* W = (sel == 0) ? Wq : (sel == 1) ? Wk : (sel == 2) ? Wv : Wsk;
        float w = W[((size_t)l * HID + k) * HID + jj];
        size_t off = ((size_t)l * 1024 + j) * HID + k;
        WtH[off] = bf16_bits(w);
        WtL[off] = bf16_bits(w - bf16_round(w));
    } else if (b < 4224) {                // pack cp_W1^T: 128*256
        int idx = (b - 4096) * 256 + t;
        int k = idx & 255, n = idx >> 8;
        float w = cp_W1[(size_t)k * 128 + n];
        Wt1H[idx] = bf16_bits(w);
        Wt1L[idx] = bf16_bits(w - bf16_round(w));
    } else if (b < 4480) {                // wcomb: (l,f) = 256 blocks
        int lf = b - 4224;
        int l = lf >> 6, f = lf & 63;
        const float* Wl = We + (size_t)l * HID * HID;
        const float* er = enc_We + (size_t)f * HID;
        float s = 0.f;
        for (int k = 0; k < HID; k++) s = fmaf(er[k], Wl[(size_t)k * HID + t], s);
        Wc [((size_t)l * EFD + f) * HID + t] = s;
        WcT[((size_t)l * HID + t) * EFD + f] = s;
    } else if (b < 4484) {                // bcomb
        int l = b - 4480;
        const float* Wl = We + (size_t)l * HID * HID;
        float s = 0.f;
        for (int k = 0; k < HID; k++) s = fmaf(enc_be[k], Wl[(size_t)k * HID + t], s);
        bcomb[l * HID + t] = s;
    } else if (b < 4500) {                // pack_b
        int i = (b - 4484) * 256 + t;
        int j = i & 1023, l = i >> 10;
        int sel = j >> 8, jj = j & 255;
        const float* B = (sel == 0) ? bq : (sel == 1) ? bk : (sel == 2) ? bv : bsk;
        bpack[i] = B[l * HID + jj];
    } else if (b < 4580) {                // zero pad rows of Abf
        int idx = (b - 4500) * 256 + t;
        size_t off = (size_t)NN * HID + idx;
        AH[off] = 0;
        AL[off] = 0;
    } else {                              // zero counts + cursor
        int i = (b - 4580) * 256 + t;
        if (i < NN) { counts[i] = 0; cursor[i] = 0; }
    }
}
#define PREP_BLOCKS (4580 + (NN + 255) / 256)

// ---------------- CSR build ----------------
__global__ void hist_kernel(const int* __restrict__ dst, int* __restrict__ counts) {
    int e = blockIdx.x * 256 + threadIdx.x;
    if (e < EE) atomicAdd(&counts[dst[e]], 1);
}
// warp-shuffle scan: 1024 threads, 4 syncs per 1024-chunk
__global__ void scan_kernel(const int* __restrict__ counts, int* __restrict__ rowptr, int n) {
    __shared__ int wsum[32];
    __shared__ int carry_s;
    const int tid = threadIdx.x, lane = tid & 31, warp = tid >> 5;
    if (tid == 0) carry_s = 0;
    __syncthreads();
    for (int base = 0; base < n; base += 1024) {
        int i = base + tid;
        int x = (i < n) ? counts[i] : 0;
#pragma unroll
        for (int off = 1; off < 32; off <<= 1) {
            int tv = __shfl_up_sync(0xffffffffu, x, off);
            if (lane >= off) x += tv;
        }
        if (lane == 31) wsum[warp] = x;
        __syncthreads();
        if (warp == 0) {
            int y = wsum[lane];
#pragma unroll
            for (int off = 1; off < 32; off <<= 1) {
                int tv = __shfl_up_sync(0xffffffffu, y, off);
                if (lane >= off) y += tv;
            }
            wsum[lane] = y;
        }
        __syncthreads();
        int pre = (warp > 0) ? wsum[warp - 1] : 0;
        if (i < n) rowptr[i + 1] = x + pre + carry_s;
        __syncthreads();
        if (tid == 0) carry_s += wsum[31];
        __syncthreads();
    }
    if (tid == 0) rowptr[0] = 0;
}
__global__ void scatter_kernel(const int* __restrict__ dst, const int* __restrict__ rowptr,
                               int* __restrict__ cursor, int* __restrict__ perm) {
    int e = blockIdx.x * 256 + threadIdx.x;
    if (e >= EE) return;
    int d = dst[e];
    int pos = rowptr[d] + atomicAdd(&cursor[d], 1);
    perm[pos] = e;
}

// ---------------- fused attention + residual + LN + bf16 conversion ----------------
__global__ __launch_bounds__(256) void attn_kernel(
    const float* __restrict__ QKVS, const float* __restrict__ edge_attr,
    const float* __restrict__ Wcomb, const float* __restrict__ WcombT,
    const float* __restrict__ bcomb,
    const int* __restrict__ src, const int* __restrict__ perm,
    const int* __restrict__ rowptr,
    float* __restrict__ h, const float* __restrict__ lng, const float* __restrict__ lnb,
    unsigned short* __restrict__ AbfH, unsigned short* __restrict__ AbfL,
    float* __restrict__ out_h)
{
    __shared__ int   sh_s[TILE];
    __shared__ float sh_ea[TILE * EFD];
    __shared__ float red[8];

    const int n    = blockIdx.x;
    const int warp = threadIdx.x >> 5;
    const int lane = threadIdx.x & 31;
    const int col  = warp * DD + lane;
    const int beg = rowptr[n], end = rowptr[n + 1];
    const float* Kpl = QKVS + PLANE;
    const float* Vpl = QKVS + 2 * PLANE;
    const float q = QKVS[(size_t)n * HID + col];
    const int hb = warp * DD;

    float qw0 = 0.f, qw1 = 0.f;
#pragma unroll
    for (int d = 0; d < 32; d++) {
        float qd = __shfl_sync(0xffffffffu, q, d);
        qw0 = fmaf(qd, WcombT[(size_t)(hb + d) * EFD + lane], qw0);
        qw1 = fmaf(qd, WcombT[(size_t)(hb + d) * EFD + 32 + lane], qw1);
    }

    float m = -3.0e38f, s = 0.f, acc = 0.f, wea0 = 0.f, wea1 = 0.f;
    const float inv_sqrt_d = 0.17677669529663687f;

    for (int base = beg; base < end; base += TILE) {
        int cnt = min(TILE, end - base);
        __syncthreads();
        for (int t = threadIdx.x; t < cnt; t += 256)
            sh_s[t] = src[perm[base + t]];
        __syncthreads();
        for (int t = threadIdx.x; t < cnt * 16; t += 256) {
            int j = t >> 4, p4 = (t & 15) * 4;
            *(float4*)&sh_ea[j * EFD + p4] =
                *(const float4*)(edge_attr + (size_t)perm[base + j] * EFD + p4);
        }
        __syncthreads();

        int j = 0;
        for (; j + 4 <= cnt; j += 4) {
            float ea0[4], ea1[4], kk[4], vv[4], sc[4];
#pragma unroll
            for (int i = 0; i < 4; i++) {
                int sn = sh_s[j + i];
                ea0[i] = sh_ea[(j + i) * EFD + lane];
                ea1[i] = sh_ea[(j + i) * EFD + 32 + lane];
                kk[i]  = Kpl[(size_t)sn * HID + col];
                vv[i]  = Vpl[(size_t)sn * HID + col];
            }
#pragma unroll
            for (int i = 0; i < 4; i++)
                sc[i] = fmaf(q, kk[i], fmaf(qw0, ea0[i], qw1 * ea1[i]));
#pragma unroll
            for (int i = 0; i < 4; i++)
                sc[i] = warp_sum(sc[i]) * inv_sqrt_d;

            float mn = fmaxf(m, fmaxf(fmaxf(sc[0], sc[1]), fmaxf(sc[2], sc[3])));
            float scale = __expf(m - mn);
            float p0 = __expf(sc[0] - mn), p1 = __expf(sc[1] - mn);
            float p2 = __expf(sc[2] - mn), p3 = __expf(sc[3] - mn);
            s    = fmaf(s, scale, ((p0 + p1) + (p2 + p3)));
            acc  = fmaf(acc, scale,
                   fmaf(p0, vv[0], fmaf(p1, vv[1], fmaf(p2, vv[2], p3 * vv[3]))));
            wea0 = fmaf(wea0, scale,
                   fmaf(p0, ea0[0], fmaf(p1, ea0[1], fmaf(p2, ea0[2], p3 * ea0[3]))));
            wea1 = fmaf(wea1, scale,
                   fmaf(p0, ea1[0], fmaf(p1, ea1[1], fmaf(p2, ea1[2], p3 * ea1[3]))));
            m = mn;
        }
        for (; j < cnt; j++) {
            int sn = sh_s[j];
            float ea0 = sh_ea[j * EFD + lane];
            float ea1 = sh_ea[j * EFD + 32 + lane];
            float kk = Kpl[(size_t)sn * HID + col];
            float vv = Vpl[(size_t)sn * HID + col];
            float part = fmaf(q, kk, fmaf(qw0, ea0, qw1 * ea1));
            float sc = warp_sum(part) * inv_sqrt_d;
            float mn = fmaxf(m, sc);
            float scale = __expf(m - mn);
            float p     = __expf(sc - mn);
            s    = fmaf(s,    scale, p);
            acc  = fmaf(acc,  scale, p * vv);
            wea0 = fmaf(wea0, scale, p * ea0);
            wea1 = fmaf(wea1, scale, p * ea1);
            m = mn;
        }
    }

    float kec = 0.f;
#pragma unroll
    for (int f = 0; f < 32; f++) {
        float w0 = __shfl_sync(0xffffffffu, wea0, f);
        float w1 = __shfl_sync(0xffffffffu, wea1, f);
        kec = fmaf(w0, Wcomb[(size_t)f * HID + col], kec);
        kec = fmaf(w1, Wcomb[(size_t)(f + 32) * HID + col], kec);
    }
    float res = (acc + kec + s * bcomb[col]) / (s + 1e-16f);

    const float* SKpl = QKVS + 3 * PLANE;
    size_t idx = (size_t)n * HID + col;
    float v = h[idx] + res + SKpl[idx];

    __syncthreads();
    float ws = warp_sum(v);
    if (lane == 0) red[warp] = ws;
    __syncthreads();
    float mean = 0.f;
#pragma unroll
    for (int w = 0; w < 8; w++) mean += red[w];
    mean *= (1.0f / HID);
    __syncthreads();
    float dv = v - mean;
    float ws2 = warp_sum(dv * dv);
    if (lane == 0) red[warp] = ws2;
    __syncthreads();
    float var = 0.f;
#pragma unroll
    for (int w = 0; w < 8; w++) var += red[w];
    var *= (1.0f / HID);
    float o = dv * rsqrtf(var + 1e-5f) * lng[col] + lnb[col];
    h[idx] = o;
    if (out_h) out_h[idx] = o;

    AbfH[idx] = bf16_bits(o);
    AbfL[idx] = bf16_bits(o - bf16_round(o));
}

// ---------------- outputs ----------------
__global__ void zero_g_kernel(float* __restrict__ out) {
    out[OFF_G + threadIdx.x] = 0.f;
}
__global__ void mean_pool_kernel(const float* __restrict__ h, float* __restrict__ out) {
    int per = (NN + gridDim.x - 1) / gridDim.x;
    int r0 = blockIdx.x * per, r1 = min(NN, r0 + per);
    float s = 0.f;
    for (int r = r0; r < r1; r++) s += h[(size_t)r * HID + threadIdx.x];
    atomicAdd(&out[OFF_G + threadIdx.x], s * (1.0f / NN));
}
__global__ __launch_bounds__(256) void contagion_kernel(
    const float* __restrict__ T1, const float* __restrict__ W2,
    const float* __restrict__ b2, float* __restrict__ out)
{
    int n = blockIdx.x * 8 + (threadIdx.x >> 5);
    if (n >= NN) return;
    int lane = threadIdx.x & 31;
    float s = 0.f;
#pragma unroll
    for (int i = 0; i < 4; i++) {
        int c = lane + 32 * i;
        s = fmaf(T1[(size_t)n * 128 + c], W2[c], s);
    }
    s = warp_sum(s);
    if (lane == 0) out[OFF_C + n] = 1.f / (1.f + expf(-(s + b2[0])));
}
__global__ void systemic_kernel(const float* __restrict__ W1, const float* __restrict__ b1,
                                const float* __restrict__ W2, const float* __restrict__ b2,
                                float* __restrict__ out)
{
    __shared__ float sh[128];
    int j = threadIdx.x;
    const float* g = out + OFF_G;
    float t = b1[j];
    for (int k = 0; k < HID; k++) t = fmaf(g[k], W1[k * 128 + j], t);
    sh[j] = fmaxf(t, 0.f) * W2[j];
    __syncthreads();
    for (int off = 64; off > 0; off >>= 1) {
        if (j < off) sh[j] += sh[j + off];
        __syncthreads();
    }
    if (j == 0) out[OFF_S] = 1.f / (1.f + expf(-(sh[0] + b2[0])));
}

// ---------------- host ----------------
static inline void* sym(const void* s) { void* p = nullptr; cudaGetSymbolAddress(&p, s); return p; }

extern "C" void kernel_launch(void* const* d_in, const int* in_sizes, int n_in,
                              void* d_out, int out_size)
{
    const float* x         = (const float*)d_in[0];
    const float* edge_attr = (const float*)d_in[1];
    const int*   edge_index= (const int*)  d_in[2];
    const float* enc_Wn = (const float*)d_in[3];
    const float* enc_bn = (const float*)d_in[4];
    const float* enc_We = (const float*)d_in[5];
    const float* enc_be = (const float*)d_in[6];
    const float* Wq = (const float*)d_in[7];  const float* bq = (const float*)d_in[8];
    const float* Wk = (const float*)d_in[9];  const float* bk = (const float*)d_in[10];
    const float* Wv = (const float*)d_in[11]; const float* bv = (const float*)d_in[12];
    const float* We = (const float*)d_in[13];
    const float* Wsk= (const float*)d_in[14]; const float* bsk= (const float*)d_in[15];
    const float* ln_g = (const float*)d_in[16];
    const float* ln_b = (const float*)d_in[17];
    const float* cp_W1 = (const float*)d_in[18]; const float* cp_b1 = (const float*)d_in[19];
    const float* cp_W2 = (const float*)d_in[20]; const float* cp_b2 = (const float*)d_in[21];
    const float* sp_W1 = (const float*)d_in[22]; const float* sp_b1 = (const float*)d_in[23];
    const float* sp_W2 = (const float*)d_in[24]; const float* sp_b2 = (const float*)d_in[25];
    float* out = (float*)d_out;

    float* h    = (float*)sym(d_h);
    float* QKVS = (float*)sym(d_QKVS);
    unsigned short* AbfH = (unsigned short*)sym(d_AbfH);
    unsigned short* AbfL = (unsigned short*)sym(d_AbfL);
    unsigned short* WtH  = (unsigned short*)sym(d_WtH);
    unsigned short* WtL  = (unsigned short*)sym(d_WtL);
    unsigned short* Wt1H = (unsigned short*)sym(d_Wt1H);
    unsigned short* Wt1L = (unsigned short*)sym(d_Wt1L);
    float* bpack= (float*)sym(d_bpack);
    float* Wcomb= (float*)sym(d_Wcomb);
    float* WcombT=(float*)sym(d_WcombT);
    float* bcomb= (float*)sym(d_bcomb);
    float* T1   = (float*)sym(d_T1);
    int* counts = (int*)sym(d_counts);
    int* cursor = (int*)sym(d_cursor);
    int* rowptr = (int*)sym(d_rowptr);
    int* perm   = (int*)sym(d_perm);

    const int* src = edge_index;
    const int* dst = edge_index + EE;

    cudaFuncSetAttribute(hgemm_kernel, cudaFuncAttributeMaxDynamicSharedMemorySize,
                         2 * STAGE_BYTES);

    // idx 0: all prep
    prep_kernel<<<PREP_BLOCKS, 256>>>(Wq, Wk, Wv, Wsk, bq, bk, bv, bsk,
                                      enc_We, enc_be, We, cp_W1,
                                      WtH, WtL, Wt1H, Wt1L, bpack, Wcomb, WcombT, bcomb,
                                      AbfH, AbfL, counts, cursor);
    // idx 1: node encoder
    {
        dim3 g(HID / 128, (NN + 127) / 128);
        sgemm128<<<g, 256>>>(x, enc_Wn, enc_bn, h, NN, HID, NFD, 1, AbfH, AbfL);
    }
    // idx 2: hist
    hist_kernel<<<(EE + 255) / 256, 256>>>(dst, counts);
    // idx 3: first hgemm (target of ncu capture slot)
    {
        dim3 g(1024 / 64, NN_PAD / 128);
        hgemm_kernel<<<g, 256, 2 * STAGE_BYTES>>>(AbfH, AbfL, WtH, WtL, bpack, QKVS, 0);
    }
    // idx 4-5: scan + scatter
    scan_kernel<<<1, 1024>>>(counts, rowptr, NN);
    scatter_kernel<<<(EE + 255) / 256, 256>>>(dst, rowptr, cursor, perm);

    // layers
    for (int l = 0; l < LL; l++) {
        if (l > 0) {
            dim3 g(1024 / 64, NN_PAD / 128);
            hgemm_kernel<<<g, 256, 2 * STAGE_BYTES>>>(
                AbfH, AbfL,
                WtH + (size_t)l * 1024 * HID,
                WtL + (size_t)l * 1024 * HID,
                bpack + (size_t)l * 1024, QKVS, 0);
        }
        attn_kernel<<<NN, 256>>>(QKVS, edge_attr,
                                 Wcomb + (size_t)l * EFD * HID,
                                 WcombT + (size_t)l * HID * EFD,
                                 bcomb + (size_t)l * HID,
                                 src, perm, rowptr,
                                 h, ln_g, ln_b, AbfH, AbfL,
                                 (l == LL - 1) ? (out + OFF_H) : nullptr);
    }

    // outputs
    zero_g_kernel<<<1, HID>>>(out);
    mean_pool_kernel<<<128, HID>>>(h, out);
    {
        dim3 g(128 / 64, NN_PAD / 128);
        hgemm_kernel<<<g, 256, 2 * STAGE_BYTES>>>(AbfH, AbfL, Wt1H, Wt1L, cp_b1, T1, 1);
    }
    contagion_kernel<<<(NN + 7) / 8, 256>>>(T1, cp_W2, cp_b2, out);
    systemic_kernel<<<1, 128>>>(sp_W1, sp_b1, sp_W2, sp_b2, out);
}

// round 13
// speedup vs baseline: 1.1150x; 1.0121x over previous
#include <cuda_runtime.h>
#include <cuda_bf16.h>
#include <math.h>
#include <stdint.h>

#define NN     30000
#define NN_PAD 30080
#define EE     480000
#define NFD    128
#define EFD    64
#define HID    256
#define LL     4
#define NH     8
#define DD     32
#define TILE   64

#define OFF_H 0
#define OFF_G (NN*HID)
#define OFF_C (NN*HID + HID)
#define OFF_S (NN*HID + HID + NN)

#define PLANE ((size_t)NN * HID)

#define STAGE_BYTES 30720
#define A_ROW_B 80

// ---------------- static device scratch ----------------
__device__ float d_h   [NN*HID];
__device__ float d_QKVS[(size_t)4*NN*HID];   // planes: Q | K | V | SK
__device__ __align__(16) unsigned short d_AbfH[(size_t)NN_PAD*HID];
__device__ __align__(16) unsigned short d_AbfL[(size_t)NN_PAD*HID];
__device__ __align__(16) unsigned short d_XbfH[(size_t)NN_PAD*NFD];
__device__ __align__(16) unsigned short d_XbfL[(size_t)NN_PAD*NFD];
__device__ __align__(16) unsigned short d_WnTH[HID*NFD];             // enc_Wn^T [n=256][k=128]
__device__ __align__(16) unsigned short d_WnTL[HID*NFD];
__device__ __align__(16) unsigned short d_WtH[(size_t)LL*1024*HID];  // [l][n][k]
__device__ __align__(16) unsigned short d_WtL[(size_t)LL*1024*HID];
__device__ __align__(16) unsigned short d_Wt1H[128*HID];             // cp_W1^T
__device__ __align__(16) unsigned short d_Wt1L[128*HID];
__device__ float d_bpack[LL*1024];
__device__ float d_Wcomb [LL*EFD*HID];
__device__ float d_WcombT[LL*HID*EFD];
__device__ float d_bcomb[LL*HID];
__device__ float d_T1[NN*(HID/2)];
__device__ int   d_counts[NN];
__device__ int   d_cursor[NN];
__device__ int   d_rowptr[NN+1];
__device__ int   d_perm[EE];

// ---------------- small helpers ----------------
__device__ __forceinline__ float warp_sum(float v) {
    v += __shfl_xor_sync(0xffffffffu, v, 16);
    v += __shfl_xor_sync(0xffffffffu, v, 8);
    v += __shfl_xor_sync(0xffffffffu, v, 4);
    v += __shfl_xor_sync(0xffffffffu, v, 2);
    v += __shfl_xor_sync(0xffffffffu, v, 1);
    return v;
}
__device__ __forceinline__ unsigned short bf16_bits(float f) {
    __nv_bfloat16 b = __float2bfloat16(f);
    return *(unsigned short*)&b;
}
__device__ __forceinline__ float bf16_round(float f) {
    return __bfloat162float(__float2bfloat16(f));
}

// ---------------- PTX wrappers (plain sm_80+ features only) ----------------
__device__ __forceinline__ void cp_async16(uint32_t saddr, const void* gptr) {
    asm volatile("cp.async.cg.shared.global [%0], [%1], 16;" :: "r"(saddr), "l"(gptr));
}
__device__ __forceinline__ void cp_commit() {
    asm volatile("cp.async.commit_group;");
}
template <int N>
__device__ __forceinline__ void cp_wait() {
    asm volatile("cp.async.wait_group %0;" :: "n"(N));
}
__device__ __forceinline__ void ldsm4(uint32_t* r, uint32_t addr) {
    asm volatile("ldmatrix.sync.aligned.m8n8.x4.shared.b16 {%0,%1,%2,%3}, [%4];"
                 : "=r"(r[0]), "=r"(r[1]), "=r"(r[2]), "=r"(r[3]) : "r"(addr));
}
__device__ __forceinline__ void mma16816(float* c, const uint32_t* a, uint32_t b0, uint32_t b1) {
    asm volatile(
        "mma.sync.aligned.m16n8k16.row.col.f32.bf16.bf16.f32 "
        "{%0,%1,%2,%3}, {%4,%5,%6,%7}, {%8,%9}, {%0,%1,%2,%3};"
        : "+f"(c[0]), "+f"(c[1]), "+f"(c[2]), "+f"(c[3])
        : "r"(a[0]), "r"(a[1]), "r"(a[2]), "r"(a[3]), "r"(b0), "r"(b1));
}

// ---------------- tensor-core GEMM (bf16 hi/lo split, fp32 acc) ----------------
// mode 0: C = QKVS planes; [NN_PAD][1024] = A[.,kLen] @ Wt[1024][kLen]^T + bias
// mode 1: C = T1 [NN][128] = relu(A @ Wt1^T + bias)
// mode 2: C = h  [NN][256] = A @ WnT^T + bias; also writes d_AbfH/d_AbfL bf16 split
// 3-stage cp.async pipeline, one __syncthreads per k-chunk.
__global__ __launch_bounds__(256) void hgemm_kernel(
    const unsigned short* __restrict__ AH, const unsigned short* __restrict__ AL,
    const unsigned short* __restrict__ BH, const unsigned short* __restrict__ BL,
    const float* __restrict__ bias, float* __restrict__ C, int mode, int kLen)
{
    extern __shared__ unsigned char sm[];
    uint32_t sbase = (uint32_t)__cvta_generic_to_shared(sm);
    const int tid  = threadIdx.x;
    const int wid  = tid >> 5, lane = tid & 31;
    const int warpM = wid & 3, warpN = wid >> 2;
    const int rowBase = blockIdx.y * 128;
    const int colBase = blockIdx.x * 64;
    const int nCh = kLen >> 5;

    float acc[2][4][4];
#pragma unroll
    for (int mi = 0; mi < 2; mi++)
#pragma unroll
        for (int nf = 0; nf < 4; nf++)
#pragma unroll
            for (int k = 0; k < 4; k++) acc[mi][nf][k] = 0.f;

    const int ar  = tid >> 1;
    const int as0 = (tid & 1) * 2;
    const int br  = tid >> 2;
    const int bs  = tid & 3;

    auto issue = [&](int ch, int stage) {
        uint32_t s0 = sbase + stage * STAGE_BYTES;
        const unsigned short* gAH = AH + (size_t)(rowBase + ar) * kLen + ch * 32;
        const unsigned short* gAL = AL + (size_t)(rowBase + ar) * kLen + ch * 32;
#pragma unroll
        for (int i = 0; i < 2; i++) {
            int seg = as0 + i;
            cp_async16(s0         + ar * A_ROW_B + seg * 16, (const char*)gAH + seg * 16);
            cp_async16(s0 + 10240 + ar * A_ROW_B + seg * 16, (const char*)gAL + seg * 16);
        }
        const unsigned short* gBH = BH + (size_t)(colBase + br) * kLen + ch * 32;
        const unsigned short* gBL = BL + (size_t)(colBase + br) * kLen + ch * 32;
        cp_async16(s0 + 20480 + br * A_ROW_B + bs * 16, (const char*)gBH + bs * 16);
        cp_async16(s0 + 25600 + br * A_ROW_B + bs * 16, (const char*)gBL + bs * 16);
        cp_commit();
    };

    const uint32_t aoff = (uint32_t)(warpM * 32 + (lane & 15)) * A_ROW_B + ((lane >> 4) << 4);
    const uint32_t boff = (uint32_t)(warpN * 32 + (lane & 7) + ((lane >> 4) & 1) * 8) * A_ROW_B
                        + (((lane >> 3) & 1) << 4);

    issue(0, 0);
    if (nCh > 1) issue(1, 1);
    for (int ch = 0; ch < nCh; ch++) {
        if (ch == nCh - 1) cp_wait<0>(); else cp_wait<1>();
        __syncthreads();
        if (ch + 2 < nCh) issue(ch + 2, (ch + 2) % 3);

        uint32_t s0 = sbase + (ch % 3) * STAGE_BYTES;
#pragma unroll
        for (int kh = 0; kh < 2; kh++) {
            uint32_t kadd = kh * 32;
            uint32_t Ah[2][4], Al[2][4], Bh[2][4], Bl[2][4];
            ldsm4(Ah[0], s0 + aoff + kadd);
            ldsm4(Ah[1], s0 + aoff + 16 * A_ROW_B + kadd);
            ldsm4(Al[0], s0 + 10240 + aoff + kadd);
            ldsm4(Al[1], s0 + 10240 + aoff + 16 * A_ROW_B + kadd);
            ldsm4(Bh[0], s0 + 20480 + boff + kadd);
            ldsm4(Bh[1], s0 + 20480 + boff + 16 * A_ROW_B + kadd);
            ldsm4(Bl[0], s0 + 25600 + boff + kadd);
            ldsm4(Bl[1], s0 + 25600 + boff + 16 * A_ROW_B + kadd);
#pragma unroll
            for (int mi = 0; mi < 2; mi++)
#pragma unroll
                for (int np = 0; np < 2; np++)
#pragma unroll
                    for (int hf = 0; hf < 2; hf++) {
                        float* c = acc[mi][np * 2 + hf];
                        mma16816(c, Ah[mi], Bh[np][hf * 2], Bh[np][hf * 2 + 1]);
                        mma16816(c, Ah[mi], Bl[np][hf * 2], Bl[np][hf * 2 + 1]);
                        mma16816(c, Al[mi], Bh[np][hf * 2], Bh[np][hf * 2 + 1]);
                    }
        }
    }

    const int g = lane >> 2, tig = lane & 3;
#pragma unroll
    for (int mi = 0; mi < 2; mi++)
#pragma unroll
        for (int nf = 0; nf < 4; nf++) {
            int col = colBase + warpN * 32 + nf * 8 + tig * 2;
            float b0 = bias[col], b1 = bias[col + 1];
            int row0 = rowBase + warpM * 32 + mi * 16 + g;
            int row1 = row0 + 8;
            float v00 = acc[mi][nf][0] + b0, v01 = acc[mi][nf][1] + b1;
            float v10 = acc[mi][nf][2] + b0, v11 = acc[mi][nf][3] + b1;
            if (mode == 0) {
                int plane = col >> 8, cm = col & 255;
                float* base = C + (size_t)plane * PLANE + cm;
                if (row0 < NN) *(float2*)(base + (size_t)row0 * HID) = make_float2(v00, v01);
                if (row1 < NN) *(float2*)(base + (size_t)row1 * HID) = make_float2(v10, v11);
            } else if (mode == 1) {
                if (row0 < NN)
                    *(float2*)(C + (size_t)row0 * 128 + col) =
                        make_float2(fmaxf(v00, 0.f), fmaxf(v01, 0.f));
                if (row1 < NN)
                    *(float2*)(C + (size_t)row1 * 128 + col) =
                        make_float2(fmaxf(v10, 0.f), fmaxf(v11, 0.f));
            } else {
                if (row0 < NN) {
                    size_t off = (size_t)row0 * HID + col;
                    *(float2*)(C + off) = make_float2(v00, v01);
                    uint32_t hw = (uint32_t)bf16_bits(v00) | ((uint32_t)bf16_bits(v01) << 16);
                    uint32_t lw = (uint32_t)bf16_bits(v00 - bf16_round(v00))
                                | ((uint32_t)bf16_bits(v01 - bf16_round(v01)) << 16);
                    *(uint32_t*)(d_AbfH + off) = hw;
                    *(uint32_t*)(d_AbfL + off) = lw;
                }
                if (row1 < NN) {
                    size_t off = (size_t)row1 * HID + col;
                    *(float2*)(C + off) = make_float2(v10, v11);
                    uint32_t hw = (uint32_t)bf16_bits(v10) | ((uint32_t)bf16_bits(v11) << 16);
                    uint32_t lw = (uint32_t)bf16_bits(v10 - bf16_round(v10))
                                | ((uint32_t)bf16_bits(v11 - bf16_round(v11)) << 16);
                    *(uint32_t*)(d_AbfH + off) = hw;
                    *(uint32_t*)(d_AbfL + off) = lw;
                }
            }
        }
}

// ---------------- ONE merged prep kernel ----------------
__global__ void prep_kernel(
    const float* __restrict__ x,
    const float* __restrict__ Wq, const float* __restrict__ Wk,
    const float* __restrict__ Wv, const float* __restrict__ Wsk,
    const float* __restrict__ bq, const float* __restrict__ bk,
    const float* __restrict__ bv, const float* __restrict__ bsk,
    const float* __restrict__ enc_Wn,
    const float* __restrict__ enc_We, const float* __restrict__ enc_be,
    const float* __restrict__ We, const float* __restrict__ cp_W1,
    unsigned short* __restrict__ WtH, unsigned short* __restrict__ WtL,
    unsigned short* __restrict__ Wt1H, unsigned short* __restrict__ Wt1L,
    unsigned short* __restrict__ WnTH, unsigned short* __restrict__ WnTL,
    unsigned short* __restrict__ XH, unsigned short* __restrict__ XL,
    float* __restrict__ bpack, float* __restrict__ Wc, float* __restrict__ WcT,
    float* __restrict__ bcomb,
    unsigned short* __restrict__ AH, unsigned short* __restrict__ AL,
    int* __restrict__ counts, int* __restrict__ cursor)
{
    int b = blockIdx.x;
    int t = threadIdx.x;
    if (b < 4096) {                       // pack_wt: LL*1024*256
        int idx = b * 256 + t;
        int k = idx & 255;
        int rem = idx >> 8;
        int j = rem & 1023;
        int l = rem >> 10;
        int sel = j >> 8, jj = j & 255;
        const float* W = (sel == 0) ? Wq : (sel == 1) ? Wk : (sel == 2) ? Wv : Wsk;
        float w = W[((size_t)l * HID + k) * HID + jj];
        size_t off = ((size_t)l * 1024 + j) * HID + k;
        WtH[off] = bf16_bits(w);
        WtL[off] = bf16_bits(w - bf16_round(w));
    } else if (b < 4224) {                // pack cp_W1^T: 128*256
        int idx = (b - 4096) * 256 + t;
        int k = idx & 255, n = idx >> 8;
        float w = cp_W1[(size_t)k * 128 + n];
        Wt1H[idx] = bf16_bits(w);
        Wt1L[idx] = bf16_bits(w - bf16_round(w));
    } else if (b < 4480) {                // wcomb: (l,f) = 256 blocks
        int lf = b - 4224;
        int l = lf >> 6, f = lf & 63;
        const float* Wl = We + (size_t)l * HID * HID;
        const float* er = enc_We + (size_t)f * HID;
        float s = 0.f;
        for (int k = 0; k < HID; k++) s = fmaf(er[k], Wl[(size_t)k * HID + t], s);
        Wc [((size_t)l * EFD + f) * HID + t] = s;
        WcT[((size_t)l * HID + t) * EFD + f] = s;
    } else if (b < 4484) {                // bcomb
        int l = b - 4480;
        const float* Wl = We + (size_t)l * HID * HID;
        float s = 0.f;
        for (int k = 0; k < HID; k++) s = fmaf(enc_be[k], Wl[(size_t)k * HID + t], s);
        bcomb[l * HID + t] = s;
    } else if (b < 4500) {                // pack_b
        int i = (b - 4484) * 256 + t;
        int j = i & 1023, l = i >> 10;
        int sel = j >> 8, jj = j & 255;
        const float* B = (sel == 0) ? bq : (sel == 1) ? bk : (sel == 2) ? bv : bsk;
        bpack[i] = B[l * HID + jj];
    } else if (b < 4580) {                // zero pad rows of Abf
        int idx = (b - 4500) * 256 + t;
        size_t off = (size_t)NN * HID + idx;
        AH[off] = 0;
        AL[off] = 0;
    } else if (b < 4698) {                // zero counts + cursor
        int i = (b - 4580) * 256 + t;
        if (i < NN) { counts[i] = 0; cursor[i] = 0; }
    } else if (b < 19698) {               // pack x hi/lo: NN*NFD
        int idx = (b - 4698) * 256 + t;
        float v = x[idx];
        XH[idx] = bf16_bits(v);
        XL[idx] = bf16_bits(v - bf16_round(v));
    } else if (b < 19826) {               // pack enc_Wn^T: 256 n x 128 k
        int idx = (b - 19698) * 256 + t;
        int n = idx >> 7, k = idx & 127;
        float w = enc_Wn[(size_t)k * HID + n];
        WnTH[idx] = bf16_bits(w);
        WnTL[idx] = bf16_bits(w - bf16_round(w));
    } else {                              // zero pad rows of X: 80*128
        int idx = (b - 19826) * 256 + t;
        size_t off = (size_t)NN * NFD + idx;
        XH[off] = 0;
        XL[off] = 0;
    }
}
#define PREP_BLOCKS (19826 + 40)

// ---------------- CSR build ----------------
__global__ void hist_kernel(const int* __restrict__ dst, int* __restrict__ counts) {
    int e = blockIdx.x * 256 + threadIdx.x;
    if (e < EE) atomicAdd(&counts[dst[e]], 1);
}
// warp-shuffle scan
__global__ void scan_kernel(const int* __restrict__ counts, int* __restrict__ rowptr, int n) {
    __shared__ int wsum[32];
    __shared__ int carry_s;
    const int tid = threadIdx.x, lane = tid & 31, warp = tid >> 5;
    if (tid == 0) carry_s = 0;
    __syncthreads();
    for (int base = 0; base < n; base += 1024) {
        int i = base + tid;
        int x = (i < n) ? counts[i] : 0;
#pragma unroll
        for (int off = 1; off < 32; off <<= 1) {
            int tv = __shfl_up_sync(0xffffffffu, x, off);
            if (lane >= off) x += tv;
        }
        if (lane == 31) wsum[warp] = x;
        __syncthreads();
        if (warp == 0) {
            int y = wsum[lane];
#pragma unroll
            for (int off = 1; off < 32; off <<= 1) {
                int tv = __shfl_up_sync(0xffffffffu, y, off);
                if (lane >= off) y += tv;
            }
            wsum[lane] = y;
        }
        __syncthreads();
        int pre = (warp > 0) ? wsum[warp - 1] : 0;
        if (i < n) rowptr[i + 1] = x + pre + carry_s;
        __syncthreads();
        if (tid == 0) carry_s += wsum[31];
        __syncthreads();
    }
    if (tid == 0) rowptr[0] = 0;
}
__global__ void scatter_kernel(const int* __restrict__ dst, const int* __restrict__ rowptr,
                               int* __restrict__ cursor, int* __restrict__ perm) {
    int e = blockIdx.x * 256 + threadIdx.x;
    if (e >= EE) return;
    int d = dst[e];
    int pos = rowptr[d] + atomicAdd(&cursor[d], 1);
    perm[pos] = e;
}

// ---------------- fused attention + residual + LN + bf16 conversion ----------------
__global__ __launch_bounds__(256) void attn_kernel(
    const float* __restrict__ QKVS, const float* __restrict__ edge_attr,
    const float* __restrict__ Wcomb, const float* __restrict__ WcombT,
    const float* __restrict__ bcomb,
    const int* __restrict__ src, const int* __restrict__ perm,
    const int* __restrict__ rowptr,
    float* __restrict__ h, const float* __restrict__ lng, const float* __restrict__ lnb,
    unsigned short* __restrict__ AbfH, unsigned short* __restrict__ AbfL,
    float* __restrict__ out_h)
{
    __shared__ int   sh_s[TILE];
    __shared__ float sh_ea[TILE * EFD];
    __shared__ float red[8];

    const int n    = blockIdx.x;
    const int warp = threadIdx.x >> 5;
    const int lane = threadIdx.x & 31;
    const int col  = warp * DD + lane;
    const int beg = rowptr[n], end = rowptr[n + 1];
    const float* Kpl = QKVS + PLANE;
    const float* Vpl = QKVS + 2 * PLANE;
    const float q = QKVS[(size_t)n * HID + col];
    const int hb = warp * DD;

    float qw0 = 0.f, qw1 = 0.f;
#pragma unroll
    for (int d = 0; d < 32; d++) {
        float qd = __shfl_sync(0xffffffffu, q, d);
        qw0 = fmaf(qd, WcombT[(size_t)(hb + d) * EFD + lane], qw0);
        qw1 = fmaf(qd, WcombT[(size_t)(hb + d) * EFD + 32 + lane], qw1);
    }

    float m = -3.0e38f, s = 0.f, acc = 0.f, wea0 = 0.f, wea1 = 0.f;
    const float inv_sqrt_d = 0.17677669529663687f;

    for (int base = beg; base < end; base += TILE) {
        int cnt = min(TILE, end - base);
        __syncthreads();
        for (int t = threadIdx.x; t < cnt; t += 256)
            sh_s[t] = src[perm[base + t]];
        __syncthreads();
        for (int t = threadIdx.x; t < cnt * 16; t += 256) {
            int j = t >> 4, p4 = (t & 15) * 4;
            *(float4*)&sh_ea[j * EFD + p4] =
                *(const float4*)(edge_attr + (size_t)perm[base + j] * EFD + p4);
        }
        __syncthreads();

        int j = 0;
        for (; j + 4 <= cnt; j += 4) {
            float ea0[4], ea1[4], kk[4], vv[4], sc[4];
#pragma unroll
            for (int i = 0; i < 4; i++) {
                int sn = sh_s[j + i];
                ea0[i] = sh_ea[(j + i) * EFD + lane];
                ea1[i] = sh_ea[(j + i) * EFD + 32 + lane];
                kk[i]  = Kpl[(size_t)sn * HID + col];
                vv[i]  = Vpl[(size_t)sn * HID + col];
            }
#pragma unroll
            for (int i = 0; i < 4; i++)
                sc[i] = fmaf(q, kk[i], fmaf(qw0, ea0[i], qw1 * ea1[i]));
#pragma unroll
            for (int i = 0; i < 4; i++)
                sc[i] = warp_sum(sc[i]) * inv_sqrt_d;

            float mn = fmaxf(m, fmaxf(fmaxf(sc[0], sc[1]), fmaxf(sc[2], sc[3])));
            float scale = __expf(m - mn);
            float p0 = __expf(sc[0] - mn), p1 = __expf(sc[1] - mn);
            float p2 = __expf(sc[2] - mn), p3 = __expf(sc[3] - mn);
            s    = fmaf(s, scale, ((p0 + p1) + (p2 + p3)));
            acc  = fmaf(acc, scale,
                   fmaf(p0, vv[0], fmaf(p1, vv[1], fmaf(p2, vv[2], p3 * vv[3]))));
            wea0 = fmaf(wea0, scale,
                   fmaf(p0, ea0[0], fmaf(p1, ea0[1], fmaf(p2, ea0[2], p3 * ea0[3]))));
            wea1 = fmaf(wea1, scale,
                   fmaf(p0, ea1[0], fmaf(p1, ea1[1], fmaf(p2, ea1[2], p3 * ea1[3]))));
            m = mn;
        }
        for (; j < cnt; j++) {
            int sn = sh_s[j];
            float ea0 = sh_ea[j * EFD + lane];
            float ea1 = sh_ea[j * EFD + 32 + lane];
            float kk = Kpl[(size_t)sn * HID + col];
            float vv = Vpl[(size_t)sn * HID + col];
            float part = fmaf(q, kk, fmaf(qw0, ea0, qw1 * ea1));
            float sc = warp_sum(part) * inv_sqrt_d;
            float mn = fmaxf(m, sc);
            float scale = __expf(m - mn);
            float p     = __expf(sc - mn);
            s    = fmaf(s,    scale, p);
            acc  = fmaf(acc,  scale, p * vv);
            wea0 = fmaf(wea0, scale, p * ea0);
            wea1 = fmaf(wea1, scale, p * ea1);
            m = mn;
        }
    }

    float kec = 0.f;
#pragma unroll
    for (int f = 0; f < 32; f++) {
        float w0 = __shfl_sync(0xffffffffu, wea0, f);
        float w1 = __shfl_sync(0xffffffffu, wea1, f);
        kec = fmaf(w0, Wcomb[(size_t)f * HID + col], kec);
        kec = fmaf(w1, Wcomb[(size_t)(f + 32) * HID + col], kec);
    }
    float res = (acc + kec + s * bcomb[col]) / (s + 1e-16f);

    const float* SKpl = QKVS + 3 * PLANE;
    size_t idx = (size_t)n * HID + col;
    float v = h[idx] + res + SKpl[idx];

    __syncthreads();
    float ws = warp_sum(v);
    if (lane == 0) red[warp] = ws;
    __syncthreads();
    float mean = 0.f;
#pragma unroll
    for (int w = 0; w < 8; w++) mean += red[w];
    mean *= (1.0f / HID);
    __syncthreads();
    float dv = v - mean;
    float ws2 = warp_sum(dv * dv);
    if (lane == 0) red[warp] = ws2;
    __syncthreads();
    float var = 0.f;
#pragma unroll
    for (int w = 0; w < 8; w++) var += red[w];
    var *= (1.0f / HID);
    float o = dv * rsqrtf(var + 1e-5f) * lng[col] + lnb[col];
    h[idx] = o;
    if (out_h) out_h[idx] = o;

    AbfH[idx] = bf16_bits(o);
    AbfL[idx] = bf16_bits(o - bf16_round(o));
}

// ---------------- outputs ----------------
__global__ void zero_g_kernel(float* __restrict__ out) {
    out[OFF_G + threadIdx.x] = 0.f;
}
__global__ void mean_pool_kernel(const float* __restrict__ h, float* __restrict__ out) {
    int per = (NN + gridDim.x - 1) / gridDim.x;
    int r0 = blockIdx.x * per, r1 = min(NN, r0 + per);
    float s = 0.f;
    for (int r = r0; r < r1; r++) s += h[(size_t)r * HID + threadIdx.x];
    atomicAdd(&out[OFF_G + threadIdx.x], s * (1.0f / NN));
}
__global__ __launch_bounds__(256) void contagion_kernel(
    const float* __restrict__ T1, const float* __restrict__ W2,
    const float* __restrict__ b2, float* __restrict__ out)
{
    int n = blockIdx.x * 8 + (threadIdx.x >> 5);
    if (n >= NN) return;
    int lane = threadIdx.x & 31;
    float s = 0.f;
#pragma unroll
    for (int i = 0; i < 4; i++) {
        int c = lane + 32 * i;
        s = fmaf(T1[(size_t)n * 128 + c], W2[c], s);
    }
    s = warp_sum(s);
    if (lane == 0) out[OFF_C + n] = 1.f / (1.f + expf(-(s + b2[0])));
}
__global__ void systemic_kernel(const float* __restrict__ W1, const float* __restrict__ b1,
                                const float* __restrict__ W2, const float* __restrict__ b2,
                                float* __restrict__ out)
{
    __shared__ float sh[128];
    int j = threadIdx.x;
    const float* g = out + OFF_G;
    float t = b1[j];
    for (int k = 0; k < HID; k++) t = fmaf(g[k], W1[k * 128 + j], t);
    sh[j] = fmaxf(t, 0.f) * W2[j];
    __syncthreads();
    for (int off = 64; off > 0; off >>= 1) {
        if (j < off) sh[j] += sh[j + off];
        __syncthreads();
    }
    if (j == 0) out[OFF_S] = 1.f / (1.f + expf(-(sh[0] + b2[0])));
}

// ---------------- host ----------------
static inline void* sym(const void* s) { void* p = nullptr; cudaGetSymbolAddress(&p, s); return p; }

extern "C" void kernel_launch(void* const* d_in, const int* in_sizes, int n_in,
                              void* d_out, int out_size)
{
    const float* x         = (const float*)d_in[0];
    const float* edge_attr = (const float*)d_in[1];
    const int*   edge_index= (const int*)  d_in[2];
    const float* enc_Wn = (const float*)d_in[3];
    const float* enc_bn = (const float*)d_in[4];
    const float* enc_We = (const float*)d_in[5];
    const float* enc_be = (const float*)d_in[6];
    const float* Wq = (const float*)d_in[7];  const float* bq = (const float*)d_in[8];
    const float* Wk = (const float*)d_in[9];  const float* bk = (const float*)d_in[10];
    const float* Wv = (const float*)d_in[11]; const float* bv = (const float*)d_in[12];
    const float* We = (const float*)d_in[13];
    const float* Wsk= (const float*)d_in[14]; const float* bsk= (const float*)d_in[15];
    const float* ln_g = (const float*)d_in[16];
    const float* ln_b = (const float*)d_in[17];
    const float* cp_W1 = (const float*)d_in[18]; const float* cp_b1 = (const float*)d_in[19];
    const float* cp_W2 = (const float*)d_in[20]; const float* cp_b2 = (const float*)d_in[21];
    const float* sp_W1 = (const float*)d_in[22]; const float* sp_b1 = (const float*)d_in[23];
    const float* sp_W2 = (const float*)d_in[24]; const float* sp_b2 = (const float*)d_in[25];
    float* out = (float*)d_out;

    float* h    = (float*)sym(d_h);
    float* QKVS = (float*)sym(d_QKVS);
    unsigned short* AbfH = (unsigned short*)sym(d_AbfH);
    unsigned short* AbfL = (unsigned short*)sym(d_AbfL);
    unsigned short* XbfH = (unsigned short*)sym(d_XbfH);
    unsigned short* XbfL = (unsigned short*)sym(d_XbfL);
    unsigned short* WnTH = (unsigned short*)sym(d_WnTH);
    unsigned short* WnTL = (unsigned short*)sym(d_WnTL);
    unsigned short* WtH  = (unsigned short*)sym(d_WtH);
    unsigned short* WtL  = (unsigned short*)sym(d_WtL);
    unsigned short* Wt1H = (unsigned short*)sym(d_Wt1H);
    unsigned short* Wt1L = (unsigned short*)sym(d_Wt1L);
    float* bpack= (float*)sym(d_bpack);
    float* Wcomb= (float*)sym(d_Wcomb);
    float* WcombT=(float*)sym(d_WcombT);
    float* bcomb= (float*)sym(d_bcomb);
    float* T1   = (float*)sym(d_T1);
    int* counts = (int*)sym(d_counts);
    int* cursor = (int*)sym(d_cursor);
    int* rowptr = (int*)sym(d_rowptr);
    int* perm   = (int*)sym(d_perm);

    const int* src = edge_index;
    const int* dst = edge_index + EE;

    cudaFuncSetAttribute(hgemm_kernel, cudaFuncAttributeMaxDynamicSharedMemorySize,
                         3 * STAGE_BYTES);

    // idx 0: all prep
    prep_kernel<<<PREP_BLOCKS, 256>>>(x, Wq, Wk, Wv, Wsk, bq, bk, bv, bsk,
                                      enc_Wn, enc_We, enc_be, We, cp_W1,
                                      WtH, WtL, Wt1H, Wt1L, WnTH, WnTL, XbfH, XbfL,
                                      bpack, Wcomb, WcombT, bcomb,
                                      AbfH, AbfL, counts, cursor);
    // idx 1: node encoder via tensor cores (mode 2, K=128)
    {
        dim3 g(HID / 64, NN_PAD / 128);
        hgemm_kernel<<<g, 256, 3 * STAGE_BYTES>>>(XbfH, XbfL, WnTH, WnTL, enc_bn, h, 2, NFD);
    }
    // idx 2: hist
    hist_kernel<<<(EE + 255) / 256, 256>>>(dst, counts);
    // idx 3: first layer hgemm (ncu capture slot)
    {
        dim3 g(1024 / 64, NN_PAD / 128);
        hgemm_kernel<<<g, 256, 3 * STAGE_BYTES>>>(AbfH, AbfL, WtH, WtL, bpack, QKVS, 0, HID);
    }
    // idx 4-5: scan + scatter
    scan_kernel<<<1, 1024>>>(counts, rowptr, NN);
    scatter_kernel<<<(EE + 255) / 256, 256>>>(dst, rowptr, cursor, perm);

    // layers
    for (int l = 0; l < LL; l++) {
        if (l > 0) {
            dim3 g(1024 / 64, NN_PAD / 128);
            hgemm_kernel<<<g, 256, 3 * STAGE_BYTES>>>(
                AbfH, AbfL,
                WtH + (size_t)l * 1024 * HID,
                WtL + (size_t)l * 1024 * HID,
                bpack + (size_t)l * 1024, QKVS, 0, HID);
        }
        attn_kernel<<<NN, 256>>>(QKVS, edge_attr,
                                 Wcomb + (size_t)l * EFD * HID,
                                 WcombT + (size_t)l * HID * EFD,
                                 bcomb + (size_t)l * HID,
                                 src, perm, rowptr,
                                 h, ln_g, ln_b, AbfH, AbfL,
                                 (l == LL - 1) ? (out + OFF_H) : nullptr);
    }

    // outputs
    zero_g_kernel<<<1, HID>>>(out);
    mean_pool_kernel<<<128, HID>>>(h, out);
    {
        dim3 g(128 / 64, NN_PAD / 128);
        hgemm_kernel<<<g, 256, 3 * STAGE_BYTES>>>(AbfH, AbfL, Wt1H, Wt1L, cp_b1, T1, 1, HID);
    }
    contagion_kernel<<<(NN + 7) / 8, 256>>>(T1, cp_W2, cp_b2, out);
    systemic_kernel<<<1, 128>>>(sp_W1, sp_b1, sp_W2, sp_b2, out);
}

// round 14
// speedup vs baseline: 1.1336x; 1.0167x over previous
#include <cuda_runtime.h>
#include <cuda_bf16.h>
#include <math.h>
#include <stdint.h>

#define NN     30000
#define NN_PAD 30080
#define EE     480000
#define NFD    128
#define EFD    64
#define HID    256
#define LL     4
#define NH     8
#define DD     32
#define TILE   64

#define OFF_H 0
#define OFF_G (NN*HID)
#define OFF_C (NN*HID + HID)
#define OFF_S (NN*HID + HID + NN)

#define PLANE ((size_t)NN * HID)

#define STAGE_BYTES 30720
#define A_ROW_B 80

// ---------------- static device scratch ----------------
__device__ float d_h   [NN*HID];
__device__ float d_QKVS[(size_t)4*NN*HID];   // planes: Q | K | V | SK
__device__ __align__(16) unsigned short d_AbfH[(size_t)NN_PAD*HID];
__device__ __align__(16) unsigned short d_AbfL[(size_t)NN_PAD*HID];
__device__ __align__(16) unsigned short d_XbfH[(size_t)NN_PAD*NFD];
__device__ __align__(16) unsigned short d_XbfL[(size_t)NN_PAD*NFD];
__device__ __align__(16) unsigned short d_WnTH[HID*NFD];             // enc_Wn^T
__device__ __align__(16) unsigned short d_WnTL[HID*NFD];
__device__ __align__(16) unsigned short d_WtH[(size_t)LL*1024*HID];  // [l][n][k]
__device__ __align__(16) unsigned short d_WtL[(size_t)LL*1024*HID];
__device__ __align__(16) unsigned short d_Wt1H[128*HID];             // cp_W1^T
__device__ __align__(16) unsigned short d_Wt1L[128*HID];
__device__ float d_bpack[LL*1024];
__device__ float d_Wcomb [LL*EFD*HID];
__device__ float d_WcombT[LL*HID*EFD];
__device__ float d_bcomb[LL*HID];
__device__ float d_T1[NN*(HID/2)];
__device__ int   d_counts[NN];
__device__ int   d_cursor[NN];
__device__ int   d_rowptr[NN+1];
__device__ int   d_perm[EE];

// ---------------- small helpers ----------------
__device__ __forceinline__ float warp_sum(float v) {
    v += __shfl_xor_sync(0xffffffffu, v, 16);
    v += __shfl_xor_sync(0xffffffffu, v, 8);
    v += __shfl_xor_sync(0xffffffffu, v, 4);
    v += __shfl_xor_sync(0xffffffffu, v, 2);
    v += __shfl_xor_sync(0xffffffffu, v, 1);
    return v;
}
__device__ __forceinline__ unsigned short bf16_bits(float f) {
    __nv_bfloat16 b = __float2bfloat16(f);
    return *(unsigned short*)&b;
}
__device__ __forceinline__ float bf16_round(float f) {
    return __bfloat162float(__float2bfloat16(f));
}

// ---------------- PTX wrappers (plain sm_80+ features only) ----------------
__device__ __forceinline__ void cp_async16(uint32_t saddr, const void* gptr) {
    asm volatile("cp.async.cg.shared.global [%0], [%1], 16;" :: "r"(saddr), "l"(gptr));
}
__device__ __forceinline__ void cp_commit() {
    asm volatile("cp.async.commit_group;");
}
template <int N>
__device__ __forceinline__ void cp_wait() {
    asm volatile("cp.async.wait_group %0;" :: "n"(N));
}
__device__ __forceinline__ void ldsm4(uint32_t* r, uint32_t addr) {
    asm volatile("ldmatrix.sync.aligned.m8n8.x4.shared.b16 {%0,%1,%2,%3}, [%4];"
                 : "=r"(r[0]), "=r"(r[1]), "=r"(r[2]), "=r"(r[3]) : "r"(addr));
}
__device__ __forceinline__ void mma16816(float* c, const uint32_t* a, uint32_t b0, uint32_t b1) {
    asm volatile(
        "mma.sync.aligned.m16n8k16.row.col.f32.bf16.bf16.f32 "
        "{%0,%1,%2,%3}, {%4,%5,%6,%7}, {%8,%9}, {%0,%1,%2,%3};"
        : "+f"(c[0]), "+f"(c[1]), "+f"(c[2]), "+f"(c[3])
        : "r"(a[0]), "r"(a[1]), "r"(a[2]), "r"(a[3]), "r"(b0), "r"(b1));
}

// ---------------- tensor-core GEMM (bf16 hi/lo split, fp32 acc) ----------------
// MODE 0: C = QKVS planes; MODE 1: T1 relu; MODE 2: h + bf16 split planes.
// 2-stage cp.async pipeline, ONE __syncthreads per k-chunk, 3 CTAs/SM target.
template <int MODE, int NCH>
__global__ __launch_bounds__(256, 3) void hgemm_kernel(
    const unsigned short* __restrict__ AH, const unsigned short* __restrict__ AL,
    const unsigned short* __restrict__ BH, const unsigned short* __restrict__ BL,
    const float* __restrict__ bias, float* __restrict__ C)
{
    constexpr int kLen = NCH * 32;
    extern __shared__ unsigned char sm[];
    uint32_t sbase = (uint32_t)__cvta_generic_to_shared(sm);
    const int tid  = threadIdx.x;
    const int wid  = tid >> 5, lane = tid & 31;
    const int warpM = wid & 3, warpN = wid >> 2;
    const int rowBase = blockIdx.y * 128;
    const int colBase = blockIdx.x * 64;

    float acc[2][4][4];
#pragma unroll
    for (int mi = 0; mi < 2; mi++)
#pragma unroll
        for (int nf = 0; nf < 4; nf++)
#pragma unroll
            for (int k = 0; k < 4; k++) acc[mi][nf][k] = 0.f;

    const int ar  = tid >> 1;
    const int as0 = (tid & 1) * 2;
    const int br  = tid >> 2;
    const int bs  = tid & 3;

    auto issue = [&](int ch, int stage) {
        uint32_t s0 = sbase + stage * STAGE_BYTES;
        const unsigned short* gAH = AH + (size_t)(rowBase + ar) * kLen + ch * 32;
        const unsigned short* gAL = AL + (size_t)(rowBase + ar) * kLen + ch * 32;
#pragma unroll
        for (int i = 0; i < 2; i++) {
            int seg = as0 + i;
            cp_async16(s0         + ar * A_ROW_B + seg * 16, (const char*)gAH + seg * 16);
            cp_async16(s0 + 10240 + ar * A_ROW_B + seg * 16, (const char*)gAL + seg * 16);
        }
        const unsigned short* gBH = BH + (size_t)(colBase + br) * kLen + ch * 32;
        const unsigned short* gBL = BL + (size_t)(colBase + br) * kLen + ch * 32;
        cp_async16(s0 + 20480 + br * A_ROW_B + bs * 16, (const char*)gBH + bs * 16);
        cp_async16(s0 + 25600 + br * A_ROW_B + bs * 16, (const char*)gBL + bs * 16);
        cp_commit();
    };

    const uint32_t aoff = (uint32_t)(warpM * 32 + (lane & 15)) * A_ROW_B + ((lane >> 4) << 4);
    const uint32_t boff = (uint32_t)(warpN * 32 + (lane & 7) + ((lane >> 4) & 1) * 8) * A_ROW_B
                        + (((lane >> 3) & 1) << 4);

    issue(0, 0);
#pragma unroll
    for (int ch = 0; ch < NCH; ch++) {
        cp_wait<0>();
        __syncthreads();
        if (ch + 1 < NCH) issue(ch + 1, (ch + 1) & 1);

        uint32_t s0 = sbase + (ch & 1) * STAGE_BYTES;
#pragma unroll
        for (int kh = 0; kh < 2; kh++) {
            uint32_t kadd = kh * 32;
            uint32_t Ah[2][4], Al[2][4], Bh[2][4], Bl[2][4];
            ldsm4(Ah[0], s0 + aoff + kadd);
            ldsm4(Ah[1], s0 + aoff + 16 * A_ROW_B + kadd);
            ldsm4(Al[0], s0 + 10240 + aoff + kadd);
            ldsm4(Al[1], s0 + 10240 + aoff + 16 * A_ROW_B + kadd);
            ldsm4(Bh[0], s0 + 20480 + boff + kadd);
            ldsm4(Bh[1], s0 + 20480 + boff + 16 * A_ROW_B + kadd);
            ldsm4(Bl[0], s0 + 25600 + boff + kadd);
            ldsm4(Bl[1], s0 + 25600 + boff + 16 * A_ROW_B + kadd);
#pragma unroll
            for (int mi = 0; mi < 2; mi++)
#pragma unroll
                for (int np = 0; np < 2; np++)
#pragma unroll
                    for (int hf = 0; hf < 2; hf++) {
                        float* c = acc[mi][np * 2 + hf];
                        mma16816(c, Ah[mi], Bh[np][hf * 2], Bh[np][hf * 2 + 1]);
                        mma16816(c, Ah[mi], Bl[np][hf * 2], Bl[np][hf * 2 + 1]);
                        mma16816(c, Al[mi], Bh[np][hf * 2], Bh[np][hf * 2 + 1]);
                    }
        }
    }

    const int g = lane >> 2, tig = lane & 3;
#pragma unroll
    for (int mi = 0; mi < 2; mi++)
#pragma unroll
        for (int nf = 0; nf < 4; nf++) {
            int col = colBase + warpN * 32 + nf * 8 + tig * 2;
            float b0 = bias[col], b1 = bias[col + 1];
            int row0 = rowBase + warpM * 32 + mi * 16 + g;
            int row1 = row0 + 8;
            float v00 = acc[mi][nf][0] + b0, v01 = acc[mi][nf][1] + b1;
            float v10 = acc[mi][nf][2] + b0, v11 = acc[mi][nf][3] + b1;
            if (MODE == 0) {
                int plane = col >> 8, cm = col & 255;
                float* base = C + (size_t)plane * PLANE + cm;
                if (row0 < NN) *(float2*)(base + (size_t)row0 * HID) = make_float2(v00, v01);
                if (row1 < NN) *(float2*)(base + (size_t)row1 * HID) = make_float2(v10, v11);
            } else if (MODE == 1) {
                if (row0 < NN)
                    *(float2*)(C + (size_t)row0 * 128 + col) =
                        make_float2(fmaxf(v00, 0.f), fmaxf(v01, 0.f));
                if (row1 < NN)
                    *(float2*)(C + (size_t)row1 * 128 + col) =
                        make_float2(fmaxf(v10, 0.f), fmaxf(v11, 0.f));
            } else {
                if (row0 < NN) {
                    size_t off = (size_t)row0 * HID + col;
                    *(float2*)(C + off) = make_float2(v00, v01);
                    uint32_t hw = (uint32_t)bf16_bits(v00) | ((uint32_t)bf16_bits(v01) << 16);
                    uint32_t lw = (uint32_t)bf16_bits(v00 - bf16_round(v00))
                                | ((uint32_t)bf16_bits(v01 - bf16_round(v01)) << 16);
                    *(uint32_t*)(d_AbfH + off) = hw;
                    *(uint32_t*)(d_AbfL + off) = lw;
                }
                if (row1 < NN) {
                    size_t off = (size_t)row1 * HID + col;
                    *(float2*)(C + off) = make_float2(v10, v11);
                    uint32_t hw = (uint32_t)bf16_bits(v10) | ((uint32_t)bf16_bits(v11) << 16);
                    uint32_t lw = (uint32_t)bf16_bits(v10 - bf16_round(v10))
                                | ((uint32_t)bf16_bits(v11 - bf16_round(v11)) << 16);
                    *(uint32_t*)(d_AbfH + off) = hw;
                    *(uint32_t*)(d_AbfL + off) = lw;
                }
            }
        }
}

// ---------------- ONE merged prep kernel ----------------
__global__ void prep_kernel(
    const float* __restrict__ x,
    const float* __restrict__ Wq, const float* __restrict__ Wk,
    const float* __restrict__ Wv, const float* __restrict__ Wsk,
    const float* __restrict__ bq, const float* __restrict__ bk,
    const float* __restrict__ bv, const float* __restrict__ bsk,
    const float* __restrict__ enc_Wn,
    const float* __restrict__ enc_We, const float* __restrict__ enc_be,
    const float* __restrict__ We, const float* __restrict__ cp_W1,
    unsigned short* __restrict__ WtH, unsigned short* __restrict__ WtL,
    unsigned short* __restrict__ Wt1H, unsigned short* __restrict__ Wt1L,
    unsigned short* __restrict__ WnTH, unsigned short* __restrict__ WnTL,
    unsigned short* __restrict__ XH, unsigned short* __restrict__ XL,
    float* __restrict__ bpack, float* __restrict__ Wc, float* __restrict__ WcT,
    float* __restrict__ bcomb,
    unsigned short* __restrict__ AH, unsigned short* __restrict__ AL,
    int* __restrict__ counts, int* __restrict__ cursor)
{
    int b = blockIdx.x;
    int t = threadIdx.x;
    if (b < 4096) {
        int idx = b * 256 + t;
        int k = idx & 255;
        int rem = idx >> 8;
        int j = rem & 1023;
        int l = rem >> 10;
        int sel = j >> 8, jj = j & 255;
        const float* W = (sel == 0) ? Wq : (sel == 1) ? Wk : (sel == 2) ? Wv : Wsk;
        float w = W[((size_t)l * HID + k) * HID + jj];
        size_t off = ((size_t)l * 1024 + j) * HID + k;
        WtH[off] = bf16_bits(w);
        WtL[off] = bf16_bits(w - bf16_round(w));
    } else if (b < 4224) {
        int idx = (b - 4096) * 256 + t;
        int k = idx & 255, n = idx >> 8;
        float w = cp_W1[(size_t)k * 128 + n];
        Wt1H[idx] = bf16_bits(w);
        Wt1L[idx] = bf16_bits(w - bf16_round(w));
    } else if (b < 4480) {
        int lf = b - 4224;
        int l = lf >> 6, f = lf & 63;
        const float* Wl = We + (size_t)l * HID * HID;
        const float* er = enc_We + (size_t)f * HID;
        float s = 0.f;
        for (int k = 0; k < HID; k++) s = fmaf(er[k], Wl[(size_t)k * HID + t], s);
        Wc [((size_t)l * EFD + f) * HID + t] = s;
        WcT[((size_t)l * HID + t) * EFD + f] = s;
    } else if (b < 4484) {
        int l = b - 4480;
        const float* Wl = We + (size_t)l * HID * HID;
        float s = 0.f;
        for (int k = 0; k < HID; k++) s = fmaf(enc_be[k], Wl[(size_t)k * HID + t], s);
        bcomb[l * HID + t] = s;
    } else if (b < 4500) {
        int i = (b - 4484) * 256 + t;
        int j = i & 1023, l = i >> 10;
        int sel = j >> 8, jj = j & 255;
        const float* B = (sel == 0) ? bq : (sel == 1) ? bk : (sel == 2) ? bv : bsk;
        bpack[i] = B[l * HID + jj];
    } else if (b < 4580) {
        int idx = (b - 4500) * 256 + t;
        size_t off = (size_t)NN * HID + idx;
        AH[off] = 0;
        AL[off] = 0;
    } else if (b < 4698) {
        int i = (b - 4580) * 256 + t;
        if (i < NN) { counts[i] = 0; cursor[i] = 0; }
    } else if (b < 19698) {
        int idx = (b - 4698) * 256 + t;
        float v = x[idx];
        XH[idx] = bf16_bits(v);
        XL[idx] = bf16_bits(v - bf16_round(v));
    } else if (b < 19826) {
        int idx = (b - 19698) * 256 + t;
        int n = idx >> 7, k = idx & 127;
        float w = enc_Wn[(size_t)k * HID + n];
        WnTH[idx] = bf16_bits(w);
        WnTL[idx] = bf16_bits(w - bf16_round(w));
    } else {
        int idx = (b - 19826) * 256 + t;
        size_t off = (size_t)NN * NFD + idx;
        XH[off] = 0;
        XL[off] = 0;
    }
}
#define PREP_BLOCKS (19826 + 40)

// ---------------- CSR build ----------------
__global__ void hist_kernel(const int* __restrict__ dst, int* __restrict__ counts) {
    int e = blockIdx.x * 256 + threadIdx.x;
    if (e < EE) atomicAdd(&counts[dst[e]], 1);
}
__global__ void scan_kernel(const int* __restrict__ counts, int* __restrict__ rowptr, int n) {
    __shared__ int wsum[32];
    __shared__ int carry_s;
    const int tid = threadIdx.x, lane = tid & 31, warp = tid >> 5;
    if (tid == 0) carry_s = 0;
    __syncthreads();
    for (int base = 0; base < n; base += 1024) {
        int i = base + tid;
        int x = (i < n) ? counts[i] : 0;
#pragma unroll
        for (int off = 1; off < 32; off <<= 1) {
            int tv = __shfl_up_sync(0xffffffffu, x, off);
            if (lane >= off) x += tv;
        }
        if (lane == 31) wsum[warp] = x;
        __syncthreads();
        if (warp == 0) {
            int y = wsum[lane];
#pragma unroll
            for (int off = 1; off < 32; off <<= 1) {
                int tv = __shfl_up_sync(0xffffffffu, y, off);
                if (lane >= off) y += tv;
            }
            wsum[lane] = y;
        }
        __syncthreads();
        int pre = (warp > 0) ? wsum[warp - 1] : 0;
        if (i < n) rowptr[i + 1] = x + pre + carry_s;
        __syncthreads();
        if (tid == 0) carry_s += wsum[31];
        __syncthreads();
    }
    if (tid == 0) rowptr[0] = 0;
}
__global__ void scatter_kernel(const int* __restrict__ dst, const int* __restrict__ rowptr,
                               int* __restrict__ cursor, int* __restrict__ perm) {
    int e = blockIdx.x * 256 + threadIdx.x;
    if (e >= EE) return;
    int d = dst[e];
    int pos = rowptr[d] + atomicAdd(&cursor[d], 1);
    perm[pos] = e;
}

// ---------------- fused attention + residual + LN + bf16 conversion ----------------
__global__ __launch_bounds__(256) void attn_kernel(
    const float* __restrict__ QKVS, const float* __restrict__ edge_attr,
    const float* __restrict__ Wcomb, const float* __restrict__ WcombT,
    const float* __restrict__ bcomb,
    const int* __restrict__ src, const int* __restrict__ perm,
    const int* __restrict__ rowptr,
    float* __restrict__ h, const float* __restrict__ lng, const float* __restrict__ lnb,
    unsigned short* __restrict__ AbfH, unsigned short* __restrict__ AbfL,
    float* __restrict__ out_h)
{
    __shared__ int   sh_s[TILE];
    __shared__ float sh_ea[TILE * EFD];
    __shared__ float red[8];

    const int n    = blockIdx.x;
    const int warp = threadIdx.x >> 5;
    const int lane = threadIdx.x & 31;
    const int col  = warp * DD + lane;
    const int beg = rowptr[n], end = rowptr[n + 1];
    const float* Kpl = QKVS + PLANE;
    const float* Vpl = QKVS + 2 * PLANE;
    const float q = QKVS[(size_t)n * HID + col];
    const int hb = warp * DD;

    float qw0 = 0.f, qw1 = 0.f;
#pragma unroll
    for (int d = 0; d < 32; d++) {
        float qd = __shfl_sync(0xffffffffu, q, d);
        qw0 = fmaf(qd, WcombT[(size_t)(hb + d) * EFD + lane], qw0);
        qw1 = fmaf(qd, WcombT[(size_t)(hb + d) * EFD + 32 + lane], qw1);
    }

    float m = -3.0e38f, s = 0.f, acc = 0.f, wea0 = 0.f, wea1 = 0.f;
    const float inv_sqrt_d = 0.17677669529663687f;

    for (int base = beg; base < end; base += TILE) {
        int cnt = min(TILE, end - base);
        __syncthreads();
        for (int t = threadIdx.x; t < cnt; t += 256)
            sh_s[t] = src[perm[base + t]];
        __syncthreads();
        for (int t = threadIdx.x; t < cnt * 16; t += 256) {
            int j = t >> 4, p4 = (t & 15) * 4;
            *(float4*)&sh_ea[j * EFD + p4] =
                *(const float4*)(edge_attr + (size_t)perm[base + j] * EFD + p4);
        }
        __syncthreads();

        int j = 0;
        for (; j + 4 <= cnt; j += 4) {
            float ea0[4], ea1[4], kk[4], vv[4], sc[4];
#pragma unroll
            for (int i = 0; i < 4; i++) {
                int sn = sh_s[j + i];
                ea0[i] = sh_ea[(j + i) * EFD + lane];
                ea1[i] = sh_ea[(j + i) * EFD + 32 + lane];
                kk[i]  = Kpl[(size_t)sn * HID + col];
                vv[i]  = Vpl[(size_t)sn * HID + col];
            }
#pragma unroll
            for (int i = 0; i < 4; i++)
                sc[i] = fmaf(q, kk[i], fmaf(qw0, ea0[i], qw1 * ea1[i]));
#pragma unroll
            for (int i = 0; i < 4; i++)
                sc[i] = warp_sum(sc[i]) * inv_sqrt_d;

            float mn = fmaxf(m, fmaxf(fmaxf(sc[0], sc[1]), fmaxf(sc[2], sc[3])));
            float scale = __expf(m - mn);
            float p0 = __expf(sc[0] - mn), p1 = __expf(sc[1] - mn);
            float p2 = __expf(sc[2] - mn), p3 = __expf(sc[3] - mn);
            s    = fmaf(s, scale, ((p0 + p1) + (p2 + p3)));
            acc  = fmaf(acc, scale,
                   fmaf(p0, vv[0], fmaf(p1, vv[1], fmaf(p2, vv[2], p3 * vv[3]))));
            wea0 = fmaf(wea0, scale,
                   fmaf(p0, ea0[0], fmaf(p1, ea0[1], fmaf(p2, ea0[2], p3 * ea0[3]))));
            wea1 = fmaf(wea1, scale,
                   fmaf(p0, ea1[0], fmaf(p1, ea1[1], fmaf(p2, ea1[2], p3 * ea1[3]))));
            m = mn;
        }
        for (; j < cnt; j++) {
            int sn = sh_s[j];
            float ea0 = sh_ea[j * EFD + lane];
            float ea1 = sh_ea[j * EFD + 32 + lane];
            float kk = Kpl[(size_t)sn * HID + col];
            float vv = Vpl[(size_t)sn * HID + col];
            float part = fmaf(q, kk, fmaf(qw0, ea0, qw1 * ea1));
            float sc = warp_sum(part) * inv_sqrt_d;
            float mn = fmaxf(m, sc);
            float scale = __expf(m - mn);
            float p     = __expf(sc - mn);
            s    = fmaf(s,    scale, p);
            acc  = fmaf(acc,  scale, p * vv);
            wea0 = fmaf(wea0, scale, p * ea0);
            wea1 = fmaf(wea1, scale, p * ea1);
            m = mn;
        }
    }

    float kec = 0.f;
#pragma unroll
    for (int f = 0; f < 32; f++) {
        float w0 = __shfl_sync(0xffffffffu, wea0, f);
        float w1 = __shfl_sync(0xffffffffu, wea1, f);
        kec = fmaf(w0, Wcomb[(size_t)f * HID + col], kec);
        kec = fmaf(w1, Wcomb[(size_t)(f + 32) * HID + col], kec);
    }
    float res = (acc + kec + s * bcomb[col]) / (s + 1e-16f);

    const float* SKpl = QKVS + 3 * PLANE;
    size_t idx = (size_t)n * HID + col;
    float v = h[idx] + res + SKpl[idx];

    __syncthreads();
    float ws = warp_sum(v);
    if (lane == 0) red[warp] = ws;
    __syncthreads();
    float mean = 0.f;
#pragma unroll
    for (int w = 0; w < 8; w++) mean += red[w];
    mean *= (1.0f / HID);
    __syncthreads();
    float dv = v - mean;
    float ws2 = warp_sum(dv * dv);
    if (lane == 0) red[warp] = ws2;
    __syncthreads();
    float var = 0.f;
#pragma unroll
    for (int w = 0; w < 8; w++) var += red[w];
    var *= (1.0f / HID);
    float o = dv * rsqrtf(var + 1e-5f) * lng[col] + lnb[col];
    h[idx] = o;
    if (out_h) out_h[idx] = o;

    AbfH[idx] = bf16_bits(o);
    AbfL[idx] = bf16_bits(o - bf16_round(o));
}

// ---------------- outputs ----------------
__global__ void zero_g_kernel(float* __restrict__ out) {
    out[OFF_G + threadIdx.x] = 0.f;
}
__global__ void mean_pool_kernel(const float* __restrict__ h, float* __restrict__ out) {
    int per = (NN + gridDim.x - 1) / gridDim.x;
    int r0 = blockIdx.x * per, r1 = min(NN, r0 + per);
    float s = 0.f;
    for (int r = r0; r < r1; r++) s += h[(size_t)r * HID + threadIdx.x];
    atomicAdd(&out[OFF_G + threadIdx.x], s * (1.0f / NN));
}
__global__ __launch_bounds__(256) void contagion_kernel(
    const float* __restrict__ T1, const float* __restrict__ W2,
    const float* __restrict__ b2, float* __restrict__ out)
{
    int n = blockIdx.x * 8 + (threadIdx.x >> 5);
    if (n >= NN) return;
    int lane = threadIdx.x & 31;
    float s = 0.f;
#pragma unroll
    for (int i = 0; i < 4; i++) {
        int c = lane + 32 * i;
        s = fmaf(T1[(size_t)n * 128 + c], W2[c], s);
    }
    s = warp_sum(s);
    if (lane == 0) out[OFF_C + n] = 1.f / (1.f + expf(-(s + b2[0])));
}
__global__ void systemic_kernel(const float* __restrict__ W1, const float* __restrict__ b1,
                                const float* __restrict__ W2, const float* __restrict__ b2,
                                float* __restrict__ out)
{
    __shared__ float sh[128];
    int j = threadIdx.x;
    const float* g = out + OFF_G;
    float t = b1[j];
    for (int k = 0; k < HID; k++) t = fmaf(g[k], W1[k * 128 + j], t);
    sh[j] = fmaxf(t, 0.f) * W2[j];
    __syncthreads();
    for (int off = 64; off > 0; off >>= 1) {
        if (j < off) sh[j] += sh[j + off];
        __syncthreads();
    }
    if (j == 0) out[OFF_S] = 1.f / (1.f + expf(-(sh[0] + b2[0])));
}

// ---------------- host ----------------
static inline void* sym(const void* s) { void* p = nullptr; cudaGetSymbolAddress(&p, s); return p; }

extern "C" void kernel_launch(void* const* d_in, const int* in_sizes, int n_in,
                              void* d_out, int out_size)
{
    const float* x         = (const float*)d_in[0];
    const float* edge_attr = (const float*)d_in[1];
    const int*   edge_index= (const int*)  d_in[2];
    const float* enc_Wn = (const float*)d_in[3];
    const float* enc_bn = (const float*)d_in[4];
    const float* enc_We = (const float*)d_in[5];
    const float* enc_be = (const float*)d_in[6];
    const float* Wq = (const float*)d_in[7];  const float* bq = (const float*)d_in[8];
    const float* Wk = (const float*)d_in[9];  const float* bk = (const float*)d_in[10];
    const float* Wv = (const float*)d_in[11]; const float* bv = (const float*)d_in[12];
    const float* We = (const float*)d_in[13];
    const float* Wsk= (const float*)d_in[14]; const float* bsk= (const float*)d_in[15];
    const float* ln_g = (const float*)d_in[16];
    const float* ln_b = (const float*)d_in[17];
    const float* cp_W1 = (const float*)d_in[18]; const float* cp_b1 = (const float*)d_in[19];
    const float* cp_W2 = (const float*)d_in[20]; const float* cp_b2 = (const float*)d_in[21];
    const float* sp_W1 = (const float*)d_in[22]; const float* sp_b1 = (const float*)d_in[23];
    const float* sp_W2 = (const float*)d_in[24]; const float* sp_b2 = (const float*)d_in[25];
    float* out = (float*)d_out;

    float* h    = (float*)sym(d_h);
    float* QKVS = (float*)sym(d_QKVS);
    unsigned short* AbfH = (unsigned short*)sym(d_AbfH);
    unsigned short* AbfL = (unsigned short*)sym(d_AbfL);
    unsigned short* XbfH = (unsigned short*)sym(d_XbfH);
    unsigned short* XbfL = (unsigned short*)sym(d_XbfL);
    unsigned short* WnTH = (unsigned short*)sym(d_WnTH);
    unsigned short* WnTL = (unsigned short*)sym(d_WnTL);
    unsigned short* WtH  = (unsigned short*)sym(d_WtH);
    unsigned short* WtL  = (unsigned short*)sym(d_WtL);
    unsigned short* Wt1H = (unsigned short*)sym(d_Wt1H);
    unsigned short* Wt1L = (unsigned short*)sym(d_Wt1L);
    float* bpack= (float*)sym(d_bpack);
    float* Wcomb= (float*)sym(d_Wcomb);
    float* WcombT=(float*)sym(d_WcombT);
    float* bcomb= (float*)sym(d_bcomb);
    float* T1   = (float*)sym(d_T1);
    int* counts = (int*)sym(d_counts);
    int* cursor = (int*)sym(d_cursor);
    int* rowptr = (int*)sym(d_rowptr);
    int* perm   = (int*)sym(d_perm);

    const int* src = edge_index;
    const int* dst = edge_index + EE;

    cudaFuncSetAttribute(hgemm_kernel<0,8>, cudaFuncAttributeMaxDynamicSharedMemorySize,
                         2 * STAGE_BYTES);
    cudaFuncSetAttribute(hgemm_kernel<1,8>, cudaFuncAttributeMaxDynamicSharedMemorySize,
                         2 * STAGE_BYTES);
    cudaFuncSetAttribute(hgemm_kernel<2,4>, cudaFuncAttributeMaxDynamicSharedMemorySize,
                         2 * STAGE_BYTES);

    // idx 0: all prep
    prep_kernel<<<PREP_BLOCKS, 256>>>(x, Wq, Wk, Wv, Wsk, bq, bk, bv, bsk,
                                      enc_Wn, enc_We, enc_be, We, cp_W1,
                                      WtH, WtL, Wt1H, Wt1L, WnTH, WnTL, XbfH, XbfL,
                                      bpack, Wcomb, WcombT, bcomb,
                                      AbfH, AbfL, counts, cursor);
    // idx 1: node encoder via tensor cores
    {
        dim3 g(HID / 64, NN_PAD / 128);
        hgemm_kernel<2,4><<<g, 256, 2 * STAGE_BYTES>>>(XbfH, XbfL, WnTH, WnTL, enc_bn, h);
    }
    // idx 2: hist
    hist_kernel<<<(EE + 255) / 256, 256>>>(dst, counts);
    // idx 3: first layer hgemm (ncu capture slot)
    {
        dim3 g(1024 / 64, NN_PAD / 128);
        hgemm_kernel<0,8><<<g, 256, 2 * STAGE_BYTES>>>(AbfH, AbfL, WtH, WtL, bpack, QKVS);
    }
    // idx 4-5: scan + scatter
    scan_kernel<<<1, 1024>>>(counts, rowptr, NN);
    scatter_kernel<<<(EE + 255) / 256, 256>>>(dst, rowptr, cursor, perm);

    // layers
    for (int l = 0; l < LL; l++) {
        if (l > 0) {
            dim3 g(1024 / 64, NN_PAD / 128);
            hgemm_kernel<0,8><<<g, 256, 2 * STAGE_BYTES>>>(
                AbfH, AbfL,
                WtH + (size_t)l * 1024 * HID,
                WtL + (size_t)l * 1024 * HID,
                bpack + (size_t)l * 1024, QKVS);
        }
        attn_kernel<<<NN, 256>>>(QKVS, edge_attr,
                                 Wcomb + (size_t)l * EFD * HID,
                                 WcombT + (size_t)l * HID * EFD,
                                 bcomb + (size_t)l * HID,
                                 src, perm, rowptr,
                                 h, ln_g, ln_b, AbfH, AbfL,
                                 (l == LL - 1) ? (out + OFF_H) : nullptr);
    }

    // outputs
    zero_g_kernel<<<1, HID>>>(out);
    mean_pool_kernel<<<128, HID>>>(h, out);
    {
        dim3 g(128 / 64, NN_PAD / 128);
        hgemm_kernel<1,8><<<g, 256, 2 * STAGE_BYTES>>>(AbfH, AbfL, Wt1H, Wt1L, cp_b1, T1);
    }
    contagion_kernel<<<(NN + 7) / 8, 256>>>(T1, cp_W2, cp_b2, out);
    systemic_kernel<<<1, 128>>>(sp_W1, sp_b1, sp_W2, sp_b2, out);
}